// round 2
// baseline (speedup 1.0000x reference)
#include <cuda_runtime.h>
#include <math.h>
#include <stdint.h>

#define D 128
#define BATCH 1024
#define MAXLEN 160
#define NMAX 114000
#define VMAX 50048

// ---------------- device scratch (no allocations allowed) ----------------
__device__ __align__(16) float g_csrc[D];
__device__ __align__(16) float g_cdst[D];
__device__ __align__(16) float g_ddot[512];
__device__ __align__(16) float g_pvs[VMAX];
__device__ __align__(16) float g_pvd[VMAX];
__device__ int   g_starts[BATCH];
__device__ __align__(16) float g_Wt[6 * D * D];        // transposed weights: q,k,v,o,f1,f2
__device__ __align__(16) float g_H  [(size_t)NMAX * D];
__device__ __align__(16) float g_Qn [(size_t)NMAX * D];
__device__ __align__(16) float g_q  [(size_t)NMAX * D];
__device__ __align__(16) float g_k  [(size_t)NMAX * D];
__device__ __align__(16) float g_v  [(size_t)NMAX * D];
__device__ __align__(16) float g_ctx[(size_t)NMAX * D];
__device__ __align__(16) float g_t1 [(size_t)NMAX * D];
__device__ __align__(16) float g_o2 [(size_t)NMAX * D];
__device__ __align__(16) float g_f1 [(size_t)NMAX * D];
__device__ __align__(16) float g_fin[(size_t)NMAX * D];

__device__ __forceinline__ float wsum(float v) {
#pragma unroll
    for (int o = 16; o; o >>= 1) v += __shfl_xor_sync(0xffffffffu, v, o);
    return v;
}

__device__ __forceinline__ uint32_t f2tf32(float f) {
    uint32_t u;
    asm("cvt.rna.tf32.f32 %0, %1;" : "=r"(u) : "f"(f));
    return u;
}

// ---------------- tiny precompute kernels ----------------
__global__ void k_cvec(const float* __restrict__ W, const float* __restrict__ as,
                       const float* __restrict__ ad) {
    int k = threadIdx.x;
    float s = 0.f, d = 0.f;
    for (int j = 0; j < D; j++) {
        float w = W[j * D + k];
        s += as[j] * w;
        d += ad[j] * w;
    }
    g_csrc[k] = s;
    g_cdst[k] = d;
}

__global__ void k_ddot(const float* __restrict__ dd) {
    int t = blockIdx.x * 128 + threadIdx.x;
    float s = 0.f;
    for (int k = 0; k < D; k++) s += dd[t * D + k] * g_csrc[k];
    g_ddot[t] = s;
}

__global__ void k_starts(const int* __restrict__ lens) {
    int b = threadIdx.x;
    int s = 0;
    for (int i = 0; i < b; i++) s += lens[i];
    g_starts[b] = s;
}

// transpose the 6 [128,128] weight matrices: Wt[k][j] = W[j][k]
__global__ void k_trans(const float* __restrict__ in_w, const float* __restrict__ out_w,
                        const float* __restrict__ w1, const float* __restrict__ w2) {
    int m = blockIdx.x >> 6;
    int idx = ((blockIdx.x & 63) << 8) + threadIdx.x;
    int k = idx >> 7, j = idx & 127;
    const float* src;
    if (m < 3) src = in_w + m * D * D;
    else if (m == 3) src = out_w;
    else if (m == 4) src = w1;
    else src = w2;
    g_Wt[m * D * D + k * D + j] = src[j * D + k];
}

__global__ void k_pv(const float* __restrict__ POI, int V) {
    int v = (blockIdx.x * blockDim.x + threadIdx.x) >> 5;
    int lane = threadIdx.x & 31;
    if (v >= V) return;
    float4 x  = ((const float4*)POI)[(size_t)v * 32 + lane];
    float4 cs = ((const float4*)g_csrc)[lane];
    float4 cd = ((const float4*)g_cdst)[lane];
    float ps = wsum(x.x * cs.x + x.y * cs.y + x.z * cs.z + x.w * cs.w);
    float pd = wsum(x.x * cd.x + x.y * cd.y + x.z * cd.z + x.w * cd.w);
    if (lane == 0) { g_pvs[v] = ps; g_pvd[v] = pd; }
}

// ---------------- fused GCN (2-way softmax over chain neighbors) + LayerNorm1 ----------------
__global__ void k_node(const float* __restrict__ POI, const int* __restrict__ sess,
                       const int* __restrict__ edist, const int* __restrict__ bids,
                       const int* __restrict__ npos, const int* __restrict__ lens,
                       const float* __restrict__ g1, const float* __restrict__ b1v, int N) {
    int n = (blockIdx.x * blockDim.x + threadIdx.x) >> 5;
    int lane = threadIdx.x & 31;
    if (n >= N) return;
    int b = bids[n], p = npos[n], l = lens[b];
    int vi = sess[n];
    bool hasF = (p > 0);
    bool hasB = (p < l - 1);
    float lf = hasF ? (g_pvs[vi] + g_ddot[edist[n - b - 1]]) : -3.0e38f;
    float lb = hasB ? g_pvd[vi] : -3.0e38f;
    float m = fmaxf(lf, lb);
    float ef = hasF ? __expf(lf - m) : 0.f;
    float eb = hasB ? __expf(lb - m) : 0.f;
    float inv = 1.f / (ef + eb + 1e-16f);

    float4 hv = make_float4(0.f, 0.f, 0.f, 0.f);
    if (hasF) {
        float4 xm = ((const float4*)POI)[(size_t)sess[n - 1] * 32 + lane];
        hv.x = ef * xm.x; hv.y = ef * xm.y; hv.z = ef * xm.z; hv.w = ef * xm.w;
    }
    if (hasB) {
        float4 xp = ((const float4*)POI)[(size_t)sess[n + 1] * 32 + lane];
        hv.x += eb * xp.x; hv.y += eb * xp.y; hv.z += eb * xp.z; hv.w += eb * xp.w;
    }
    hv.x *= inv; hv.y *= inv; hv.z *= inv; hv.w *= inv;
    ((float4*)g_H)[(size_t)n * 32 + lane] = hv;

    float mean = wsum(hv.x + hv.y + hv.z + hv.w) * (1.f / 128.f);
    float4 dx = make_float4(hv.x - mean, hv.y - mean, hv.z - mean, hv.w - mean);
    float var = wsum(dx.x * dx.x + dx.y * dx.y + dx.z * dx.z + dx.w * dx.w) * (1.f / 128.f);
    float r = rsqrtf(var + 1e-8f);
    float4 gg = ((const float4*)g1)[lane];
    float4 bb = ((const float4*)b1v)[lane];
    float4 qn = make_float4(dx.x * r * gg.x + bb.x, dx.y * r * gg.y + bb.y,
                            dx.z * r * gg.z + bb.z, dx.w * r * gg.w + bb.w);
    ((float4*)g_Qn)[(size_t)n * 32 + lane] = qn;
}

// ---------------- tf32 tensor-core GEMM: C[N,128] = A[N,128] @ Wt (+bias,+res,relu) ----------------
// 128 rows x 128 cols per CTA, 8 warps, each warp a 16-row stripe.
// mma.sync.aligned.m16n8k8.row.col.f32.tf32.tf32.f32
// smem: B pre-permuted into fragment order (16384 u32) + A tile 128x132 (pad) u32 tf32.
__global__ void __launch_bounds__(256, 1) gemm_tc_kernel(
    const float* __restrict__ A, const float* __restrict__ Wt,
    const float* __restrict__ bias, const float* __restrict__ res,
    float* __restrict__ C, int N, int relu) {
    extern __shared__ uint32_t sm_u[];
    uint32_t* sB = sm_u;              // [16 kstep][16 ntile][32 lane][2]
    uint32_t* sA = sm_u + 16384;      // [128][132]

    int tid = threadIdx.x;

    // ---- permute B into fragment order (coalesced global reads) ----
    for (int e = tid; e < 16384; e += 256) {
        int k = e >> 7, n = e & 127;
        uint32_t tv = f2tf32(Wt[e]);
        int kstep = k >> 3, ntile = n >> 3;
        int lane = ((n & 7) << 2) | (k & 3);
        int i = (k >> 2) & 1;
        sB[(((kstep << 4) + ntile) << 6) + (lane << 1) + i] = tv;
    }

    // ---- stage A tile (tf32-converted), zero-fill past N ----
    int row0 = blockIdx.x << 7;
    for (int it = tid; it < 128 * 32; it += 256) {
        int r = it >> 5, c4 = it & 31;
        float4 v = make_float4(0.f, 0.f, 0.f, 0.f);
        if (row0 + r < N) v = ((const float4*)A)[((size_t)(row0 + r) << 5) + c4];
        uint4 p;
        p.x = f2tf32(v.x); p.y = f2tf32(v.y); p.z = f2tf32(v.z); p.w = f2tf32(v.w);
        ((uint4*)sA)[r * 33 + c4] = p;   // 132 words/row = 33 uint4
    }
    __syncthreads();

    int warp = tid >> 5, lane = tid & 31;
    int g = lane >> 2, t = lane & 3;

    float acc[16][4];
#pragma unroll
    for (int nt = 0; nt < 16; nt++)
#pragma unroll
        for (int m = 0; m < 4; m++) acc[nt][m] = 0.f;

    const uint32_t* sAw = sA + (warp << 4) * 132;
#pragma unroll
    for (int ks = 0; ks < 16; ks++) {
        int kbase = ks * 8 + t;
        uint32_t a0 = sAw[g * 132 + kbase];
        uint32_t a1 = sAw[(g + 8) * 132 + kbase];
        uint32_t a2 = sAw[g * 132 + kbase + 4];
        uint32_t a3 = sAw[(g + 8) * 132 + kbase + 4];
        const uint32_t* bp = sB + (ks << 10) + (lane << 1);
#pragma unroll
        for (int nt = 0; nt < 16; nt++) {
            uint2 b = *(const uint2*)(bp + (nt << 6));
            asm volatile(
                "mma.sync.aligned.m16n8k8.row.col.f32.tf32.tf32.f32 "
                "{%0,%1,%2,%3}, {%4,%5,%6,%7}, {%8,%9}, {%0,%1,%2,%3};"
                : "+f"(acc[nt][0]), "+f"(acc[nt][1]), "+f"(acc[nt][2]), "+f"(acc[nt][3])
                : "r"(a0), "r"(a1), "r"(a2), "r"(a3), "r"(b.x), "r"(b.y));
        }
    }

    // ---- epilogue: bias (+relu) (+res) -> C ----
    int r1 = row0 + (warp << 4) + g;
    int r2 = r1 + 8;
#pragma unroll
    for (int nt = 0; nt < 16; nt++) {
        int col = (nt << 3) + (t << 1);
        float2 bb = *(const float2*)(bias + col);
        float2 o1 = make_float2(acc[nt][0] + bb.x, acc[nt][1] + bb.y);
        float2 o2 = make_float2(acc[nt][2] + bb.x, acc[nt][3] + bb.y);
        if (relu) {
            o1.x = fmaxf(o1.x, 0.f); o1.y = fmaxf(o1.y, 0.f);
            o2.x = fmaxf(o2.x, 0.f); o2.y = fmaxf(o2.y, 0.f);
        }
        if (r1 < N) {
            if (res) {
                float2 rv = *(const float2*)(res + (size_t)r1 * D + col);
                o1.x += rv.x; o1.y += rv.y;
            }
            *(float2*)(C + (size_t)r1 * D + col) = o1;
        }
        if (r2 < N) {
            if (res) {
                float2 rv = *(const float2*)(res + (size_t)r2 * D + col);
                o2.x += rv.x; o2.y += rv.y;
            }
            *(float2*)(C + (size_t)r2 * D + col) = o2;
        }
    }
}

// ---------------- per-session multi-head attention ----------------
__global__ void __launch_bounds__(256) attn_kernel(const int* __restrict__ lens) {
    __shared__ __align__(16) float sk[MAXLEN * 33];
    __shared__ __align__(16) float sv[MAXLEN * 33];
    __shared__ __align__(16) float ssc[8 * 176];

    int b = blockIdx.x, h = blockIdx.y;
    int l = lens[b];
    int start = g_starts[b];
    int lc = (l + 3) & ~3;
    int tid = threadIdx.x;

    for (int idx = tid; idx < lc * 32; idx += 256) {
        int r = idx >> 5, c = idx & 31;
        float kv = 0.f, vv = 0.f;
        if (r < l) {
            size_t off = (size_t)(start + r) * D + h * 32 + c;
            kv = g_k[off];
            vv = g_v[off];
        }
        sk[r * 33 + c] = kv;
        sv[r * 33 + c] = vv;
    }
    __syncthreads();

    int w = tid >> 5, lane = tid & 31;
    float* myssc = ssc + w * 176;
    const float scale = 0.17677669529663687f;

    for (int r = w; r < l; r += 8) {
        float qv = g_q[(size_t)(start + r) * D + h * 32 + lane];
        float qreg[32];
#pragma unroll
        for (int c = 0; c < 32; c++) qreg[c] = __shfl_sync(0xffffffffu, qv, c);

        float sloc[5];
        float mymax = -3.0e38f;
        int nj = 0;
        for (int j = lane; j < l; j += 32) {
            const float* kr = sk + j * 33;
            float dsum = 0.f;
#pragma unroll
            for (int c = 0; c < 32; c++) dsum += qreg[c] * kr[c];
            dsum *= scale;
            sloc[nj++] = dsum;
            mymax = fmaxf(mymax, dsum);
        }
#pragma unroll
        for (int o = 16; o; o >>= 1) mymax = fmaxf(mymax, __shfl_xor_sync(0xffffffffu, mymax, o));

        float mysum = 0.f;
        nj = 0;
        for (int j = lane; j < l; j += 32) {
            float p = __expf(sloc[nj++] - mymax);
            myssc[j] = p;
            mysum += p;
        }
        mysum = wsum(mysum);
        if (lane < 3) {
            int jj = l + lane;
            if (jj < 176) myssc[jj] = 0.f;
        }
        __syncwarp();

        float inv = 1.f / mysum;
        float acc = 0.f;
        for (int j = 0; j < lc; j += 4) {
            float4 p4 = *(const float4*)(myssc + j);
            acc += p4.x * sv[(j + 0) * 33 + lane];
            acc += p4.y * sv[(j + 1) * 33 + lane];
            acc += p4.z * sv[(j + 2) * 33 + lane];
            acc += p4.w * sv[(j + 3) * 33 + lane];
        }
        g_ctx[(size_t)(start + r) * D + h * 32 + lane] = acc * inv;
        __syncwarp();
    }
}

// ---------------- LayerNorm2 ----------------
__global__ void k_ln2(const float* __restrict__ g2, const float* __restrict__ b2v, int N) {
    int n = (blockIdx.x * blockDim.x + threadIdx.x) >> 5;
    int lane = threadIdx.x & 31;
    if (n >= N) return;
    float4 x = ((const float4*)g_t1)[(size_t)n * 32 + lane];
    float mean = wsum(x.x + x.y + x.z + x.w) * (1.f / 128.f);
    float4 dx = make_float4(x.x - mean, x.y - mean, x.z - mean, x.w - mean);
    float var = wsum(dx.x * dx.x + dx.y * dx.y + dx.z * dx.z + dx.w * dx.w) * (1.f / 128.f);
    float r = rsqrtf(var + 1e-8f);
    float4 gg = ((const float4*)g2)[lane];
    float4 bb = ((const float4*)b2v)[lane];
    float4 o = make_float4(dx.x * r * gg.x + bb.x, dx.y * r * gg.y + bb.y,
                           dx.z * r * gg.z + bb.z, dx.w * r * gg.w + bb.w);
    ((float4*)g_o2)[(size_t)n * 32 + lane] = o;
}

// ---------------- masked mean pool ----------------
__global__ void k_pool(const int* __restrict__ lens, float* __restrict__ out) {
    int b = (blockIdx.x * blockDim.x + threadIdx.x) >> 5;
    int lane = threadIdx.x & 31;
    if (b >= BATCH) return;
    int l = lens[b], s = g_starts[b];
    float4 acc = make_float4(0.f, 0.f, 0.f, 0.f);
    for (int p = 0; p < l; p++) {
        float4 v = ((const float4*)g_fin)[(size_t)(s + p) * 32 + lane];
        acc.x += v.x; acc.y += v.y; acc.z += v.z; acc.w += v.w;
    }
    float iv = 1.f / (float)l;
    float4 o = make_float4(acc.x * iv, acc.y * iv, acc.z * iv, acc.w * iv);
    ((float4*)out)[b * 32 + lane] = o;
}

// ---------------- launch ----------------
extern "C" void kernel_launch(void* const* d_in, const int* in_sizes, int n_in,
                              void* d_out, int out_size) {
    const float* POI   = (const float*)d_in[0];
    const float* ddis  = (const float*)d_in[1];
    const float* attW  = (const float*)d_in[2];
    const float* a_src = (const float*)d_in[3];
    const float* a_dst = (const float*)d_in[4];
    const float* in_w  = (const float*)d_in[5];
    const float* in_b  = (const float*)d_in[6];
    const float* out_w = (const float*)d_in[7];
    const float* out_b = (const float*)d_in[8];
    const float* ln1g  = (const float*)d_in[9];
    const float* ln1b  = (const float*)d_in[10];
    const float* ln2g  = (const float*)d_in[11];
    const float* ln2b  = (const float*)d_in[12];
    const float* w1    = (const float*)d_in[13];
    const float* b1    = (const float*)d_in[14];
    const float* w2    = (const float*)d_in[15];
    const float* b2    = (const float*)d_in[16];
    const int* sess  = (const int*)d_in[17];
    const int* edist = (const int*)d_in[18];
    const int* bids  = (const int*)d_in[20];
    const int* npos  = (const int*)d_in[21];
    const int* lens  = (const int*)d_in[22];
    int N = in_sizes[17];
    int V = in_sizes[0] / D;

    float *pH, *pQn, *pq, *pk, *pv, *pctx, *pt1, *po2, *pf1, *pfin, *pWt;
    cudaGetSymbolAddress((void**)&pH, g_H);
    cudaGetSymbolAddress((void**)&pQn, g_Qn);
    cudaGetSymbolAddress((void**)&pq, g_q);
    cudaGetSymbolAddress((void**)&pk, g_k);
    cudaGetSymbolAddress((void**)&pv, g_v);
    cudaGetSymbolAddress((void**)&pctx, g_ctx);
    cudaGetSymbolAddress((void**)&pt1, g_t1);
    cudaGetSymbolAddress((void**)&po2, g_o2);
    cudaGetSymbolAddress((void**)&pf1, g_f1);
    cudaGetSymbolAddress((void**)&pfin, g_fin);
    cudaGetSymbolAddress((void**)&pWt, g_Wt);

    size_t gsh = (size_t)(16384 + 128 * 132) * sizeof(uint32_t); // 130 KB
    cudaFuncSetAttribute(gemm_tc_kernel, cudaFuncAttributeMaxDynamicSharedMemorySize, (int)gsh);

    k_cvec<<<1, 128>>>(attW, a_src, a_dst);
    k_ddot<<<4, 128>>>(ddis);
    k_starts<<<1, 1024>>>(lens);
    k_trans<<<6 * 64, 256>>>(in_w, out_w, w1, w2);
    k_pv<<<(V + 7) / 8, 256>>>(POI, V);
    k_node<<<(N + 7) / 8, 256>>>(POI, sess, edist, bids, npos, lens, ln1g, ln1b, N);

    int gb = (N + 127) / 128;
    // Q/K/V projections
    gemm_tc_kernel<<<gb, 256, gsh>>>(pQn, pWt + 0 * D * D, in_b,       nullptr, pq, N, 0);
    gemm_tc_kernel<<<gb, 256, gsh>>>(pH,  pWt + 1 * D * D, in_b + D,   nullptr, pk, N, 0);
    gemm_tc_kernel<<<gb, 256, gsh>>>(pH,  pWt + 2 * D * D, in_b + 2*D, nullptr, pv, N, 0);
    // attention
    attn_kernel<<<dim3(BATCH, 4), 256>>>(lens);
    // out_proj + residual(Qn), then LN2
    gemm_tc_kernel<<<gb, 256, gsh>>>(pctx, pWt + 3 * D * D, out_b, pQn, pt1, N, 0);
    k_ln2<<<(N + 7) / 8, 256>>>(ln2g, ln2b, N);
    // FFN with residual
    gemm_tc_kernel<<<gb, 256, gsh>>>(po2, pWt + 4 * D * D, b1, nullptr, pf1, N, 1);
    gemm_tc_kernel<<<gb, 256, gsh>>>(pf1, pWt + 5 * D * D, b2, po2,    pfin, N, 0);
    // masked mean pool
    k_pool<<<(BATCH + 7) / 8, 256>>>(lens, (float*)d_out);
}

// round 3
// speedup vs baseline: 2.5031x; 2.5031x over previous
#include <cuda_runtime.h>
#include <math.h>
#include <stdint.h>

#define D 128
#define BATCH 1024
#define MAXLEN 160
#define NMAX 114000
#define VMAX 50048
#define MAXKT 20   // max key tiles of 8 (160/8)

// ---------------- device scratch ----------------
__device__ __align__(16) float g_csrc[D];
__device__ __align__(16) float g_cdst[D];
__device__ __align__(16) float g_ddot[512];
__device__ __align__(16) float g_pvs[VMAX];
__device__ __align__(16) float g_pvd[VMAX];
__device__ int   g_starts[BATCH];
__device__ __align__(16) uint32_t g_Wfrag[6 * D * D];   // tf32 fragment-ordered weights: q,k,v,o,f1,f2
__device__ __align__(16) float g_H  [(size_t)NMAX * D];
__device__ __align__(16) float g_Qn [(size_t)NMAX * D];
__device__ __align__(16) float g_q  [(size_t)NMAX * D];
__device__ __align__(16) float g_k  [(size_t)NMAX * D];
__device__ __align__(16) float g_v  [(size_t)NMAX * D];
__device__ __align__(16) float g_ctx[(size_t)NMAX * D];
__device__ __align__(16) float g_o2 [(size_t)NMAX * D];
__device__ __align__(16) float g_f1 [(size_t)NMAX * D];
__device__ __align__(16) float g_fin[(size_t)NMAX * D];

__device__ __forceinline__ float wsum(float v) {
#pragma unroll
    for (int o = 16; o; o >>= 1) v += __shfl_xor_sync(0xffffffffu, v, o);
    return v;
}
__device__ __forceinline__ uint32_t f2tf32(float f) {
    uint32_t u;
    asm("cvt.rna.tf32.f32 %0, %1;" : "=r"(u) : "f"(f));
    return u;
}
#define MMA_TF32(c0,c1,c2,c3,a0,a1,a2,a3,b0,b1) \
    asm volatile("mma.sync.aligned.m16n8k8.row.col.f32.tf32.tf32.f32 " \
                 "{%0,%1,%2,%3}, {%4,%5,%6,%7}, {%8,%9}, {%0,%1,%2,%3};" \
                 : "+f"(c0), "+f"(c1), "+f"(c2), "+f"(c3) \
                 : "r"(a0), "r"(a1), "r"(a2), "r"(a3), "r"(b0), "r"(b1))

// ---------------- precompute: c vectors ----------------
__global__ void k_cvec(const float* __restrict__ W, const float* __restrict__ as,
                       const float* __restrict__ ad) {
    int k = threadIdx.x;
    float s = 0.f, d = 0.f;
    for (int j = 0; j < D; j++) {
        float w = W[j * D + k];
        s += as[j] * w;
        d += ad[j] * w;
    }
    g_csrc[k] = s;
    g_cdst[k] = d;
}

// ---------------- merged precompute 2: ddot, starts, weight frags, pv ----------------
__global__ void k_pre2(const float* __restrict__ dd, const int* __restrict__ lens,
                       const float* __restrict__ in_w, const float* __restrict__ out_w,
                       const float* __restrict__ w1, const float* __restrict__ w2,
                       const float* __restrict__ POI, int V) {
    int blk = blockIdx.x;
    int tid = threadIdx.x;
    if (blk < 4) {                       // ddot: 512 entries
        int t = blk * 128 + (tid & 127);
        if (tid < 128) {
            float s = 0.f;
            for (int k = 0; k < D; k++) s += dd[t * D + k] * g_csrc[k];
            g_ddot[t] = s;
        }
    } else if (blk == 4) {               // starts: smem scan
        __shared__ int sl[BATCH];
        for (int i = tid; i < BATCH; i += 256) sl[i] = lens[i];
        __syncthreads();
        if (tid == 0) {
            int s = 0;
            for (int i = 0; i < BATCH; i++) { int t = sl[i]; sl[i] = s; s += t; }
        }
        __syncthreads();
        for (int i = tid; i < BATCH; i += 256) g_starts[i] = sl[i];
    } else if (blk < 5 + 6 * 64) {       // weight fragments
        int bb = blk - 5;
        int m = bb >> 6;
        int e = ((bb & 63) << 8) + tid;
        int k = e >> 7, n = e & 127;
        const float* src;
        if (m < 3) src = in_w + m * D * D;
        else if (m == 3) src = out_w;
        else if (m == 4) src = w1;
        else src = w2;
        float v = src[n * D + k];        // Wt[k][n] = W[n][k]
        int fo = (((k >> 3) << 4) + (n >> 3)) * 64 + ((n & 7) << 3) + ((k & 3) << 1) + ((k >> 2) & 1);
        g_Wfrag[m * D * D + fo] = f2tf32(v);
    } else {                             // pv: one warp per vocab entry
        int v = (blk - (5 + 384)) * 8 + (tid >> 5);
        int lane = tid & 31;
        if (v >= V) return;
        float4 x  = ((const float4*)POI)[(size_t)v * 32 + lane];
        float4 cs = ((const float4*)g_csrc)[lane];
        float4 cd = ((const float4*)g_cdst)[lane];
        float ps = wsum(x.x * cs.x + x.y * cs.y + x.z * cs.z + x.w * cs.w);
        float pd = wsum(x.x * cd.x + x.y * cd.y + x.z * cd.z + x.w * cd.w);
        if (lane == 0) { g_pvs[v] = ps; g_pvd[v] = pd; }
    }
}

// ---------------- fused GCN (2-way softmax) + LayerNorm1 ----------------
__global__ void k_node(const float* __restrict__ POI, const int* __restrict__ sess,
                       const int* __restrict__ edist, const int* __restrict__ bids,
                       const int* __restrict__ npos, const int* __restrict__ lens,
                       const float* __restrict__ g1, const float* __restrict__ b1v, int N) {
    int n = (blockIdx.x * blockDim.x + threadIdx.x) >> 5;
    int lane = threadIdx.x & 31;
    if (n >= N) return;
    int b = bids[n], p = npos[n], l = lens[b];
    int vi = sess[n];
    bool hasF = (p > 0);
    bool hasB = (p < l - 1);
    float lf = hasF ? (g_pvs[vi] + g_ddot[edist[n - b - 1]]) : -3.0e38f;
    float lb = hasB ? g_pvd[vi] : -3.0e38f;
    float m = fmaxf(lf, lb);
    float ef = hasF ? __expf(lf - m) : 0.f;
    float eb = hasB ? __expf(lb - m) : 0.f;
    float inv = 1.f / (ef + eb + 1e-16f);

    float4 hv = make_float4(0.f, 0.f, 0.f, 0.f);
    if (hasF) {
        float4 xm = ((const float4*)POI)[(size_t)sess[n - 1] * 32 + lane];
        hv.x = ef * xm.x; hv.y = ef * xm.y; hv.z = ef * xm.z; hv.w = ef * xm.w;
    }
    if (hasB) {
        float4 xp = ((const float4*)POI)[(size_t)sess[n + 1] * 32 + lane];
        hv.x += eb * xp.x; hv.y += eb * xp.y; hv.z += eb * xp.z; hv.w += eb * xp.w;
    }
    hv.x *= inv; hv.y *= inv; hv.z *= inv; hv.w *= inv;
    ((float4*)g_H)[(size_t)n * 32 + lane] = hv;

    float mean = wsum(hv.x + hv.y + hv.z + hv.w) * (1.f / 128.f);
    float4 dx = make_float4(hv.x - mean, hv.y - mean, hv.z - mean, hv.w - mean);
    float var = wsum(dx.x * dx.x + dx.y * dx.y + dx.z * dx.z + dx.w * dx.w) * (1.f / 128.f);
    float r = rsqrtf(var + 1e-8f);
    float4 gg = ((const float4*)g1)[lane];
    float4 bb = ((const float4*)b1v)[lane];
    float4 qn = make_float4(dx.x * r * gg.x + bb.x, dx.y * r * gg.y + bb.y,
                            dx.z * r * gg.z + bb.z, dx.w * r * gg.w + bb.w);
    ((float4*)g_Qn)[(size_t)n * 32 + lane] = qn;
}

// ---------------- GEMM building blocks ----------------
__device__ __forceinline__ void copyB(uint32_t* sB, const uint32_t* __restrict__ Bf, int tid) {
#pragma unroll
    for (int i = 0; i < 16; i++)
        ((uint4*)sB)[tid + 256 * i] = ((const uint4*)Bf)[tid + 256 * i];
}

__device__ __forceinline__ void stageA(uint32_t* sA, const float* __restrict__ A,
                                       int row0, int N, int tid) {
#pragma unroll
    for (int i = 0; i < 16; i++) {
        int idx = tid + 256 * i;
        int r = idx >> 5, c4 = idx & 31;
        float4 v = make_float4(0.f, 0.f, 0.f, 0.f);
        if (row0 + r < N) v = ((const float4*)A)[((size_t)(row0 + r) << 5) + c4];
        uint4 p;
        p.x = f2tf32(v.x); p.y = f2tf32(v.y); p.z = f2tf32(v.z); p.w = f2tf32(v.w);
        ((uint4*)sA)[r * 33 + c4] = p;
    }
}

__device__ __forceinline__ void mmaTile(const uint32_t* sA, const uint32_t* sB,
                                        int warp, int lane, float acc[16][4]) {
    int g = lane >> 2, t = lane & 3;
#pragma unroll
    for (int nt = 0; nt < 16; nt++)
#pragma unroll
        for (int m = 0; m < 4; m++) acc[nt][m] = 0.f;
    const uint32_t* sAw = sA + (warp << 4) * 132;
#pragma unroll
    for (int ks = 0; ks < 16; ks++) {
        int kbase = ks * 8 + t;
        uint32_t a0 = sAw[g * 132 + kbase];
        uint32_t a1 = sAw[(g + 8) * 132 + kbase];
        uint32_t a2 = sAw[g * 132 + kbase + 4];
        uint32_t a3 = sAw[(g + 8) * 132 + kbase + 4];
        const uint32_t* bp = sB + (ks << 10) + (lane << 1);
#pragma unroll
        for (int nt = 0; nt < 16; nt++) {
            uint2 b = *(const uint2*)(bp + (nt << 6));
            MMA_TF32(acc[nt][0], acc[nt][1], acc[nt][2], acc[nt][3],
                     a0, a1, a2, a3, b.x, b.y);
        }
    }
}

__device__ __forceinline__ void epiPlain(float acc[16][4], const float* __restrict__ bias,
                                         const float* __restrict__ res, float* __restrict__ C,
                                         int row0, int warp, int lane, int N, bool relu) {
    int g = lane >> 2, t = lane & 3;
    int r1 = row0 + (warp << 4) + g;
    int r2 = r1 + 8;
#pragma unroll
    for (int nt = 0; nt < 16; nt++) {
        int col = (nt << 3) + (t << 1);
        float2 bb = *(const float2*)(bias + col);
        float2 o1 = make_float2(acc[nt][0] + bb.x, acc[nt][1] + bb.y);
        float2 o2 = make_float2(acc[nt][2] + bb.x, acc[nt][3] + bb.y);
        if (relu) {
            o1.x = fmaxf(o1.x, 0.f); o1.y = fmaxf(o1.y, 0.f);
            o2.x = fmaxf(o2.x, 0.f); o2.y = fmaxf(o2.y, 0.f);
        }
        if (r1 < N) {
            if (res) { float2 rv = *(const float2*)(res + (size_t)r1 * D + col); o1.x += rv.x; o1.y += rv.y; }
            *(float2*)(C + (size_t)r1 * D + col) = o1;
        }
        if (r2 < N) {
            if (res) { float2 rv = *(const float2*)(res + (size_t)r2 * D + col); o2.x += rv.x; o2.y += rv.y; }
            *(float2*)(C + (size_t)r2 * D + col) = o2;
        }
    }
}

// generic GEMM: mode 0=bias, 1=bias+relu, 2=bias+res, 3=bias+res+LayerNorm2
__global__ void __launch_bounds__(256, 1) gemm_fused(
    const float* __restrict__ A, const uint32_t* __restrict__ Bfrag,
    const float* __restrict__ bias, const float* __restrict__ res,
    const float* __restrict__ lng, const float* __restrict__ lnb,
    float* __restrict__ C, int N, int mode) {
    extern __shared__ uint32_t sm_u[];
    uint32_t* sB = sm_u;
    uint32_t* sA = sm_u + 16384;
    int tid = threadIdx.x;
    copyB(sB, Bfrag, tid);
    int row0 = blockIdx.x << 7;
    stageA(sA, A, row0, N, tid);
    __syncthreads();

    int warp = tid >> 5, lane = tid & 31;
    float acc[16][4];
    mmaTile(sA, sB, warp, lane, acc);

    if (mode != 3) {
        epiPlain(acc, bias, res, C, row0, warp, lane, N, mode == 1);
        return;
    }
    // mode 3: bias + residual + LayerNorm2
    int g = lane >> 2, t = lane & 3;
    int r1 = row0 + (warp << 4) + g;
    int r2 = r1 + 8;
    float s1 = 0.f, s2 = 0.f;
#pragma unroll
    for (int nt = 0; nt < 16; nt++) {
        int col = (nt << 3) + (t << 1);
        float2 bb = *(const float2*)(bias + col);
        float2 rv1 = make_float2(0.f, 0.f), rv2 = make_float2(0.f, 0.f);
        if (r1 < N) rv1 = *(const float2*)(res + (size_t)r1 * D + col);
        if (r2 < N) rv2 = *(const float2*)(res + (size_t)r2 * D + col);
        acc[nt][0] += bb.x + rv1.x; acc[nt][1] += bb.y + rv1.y;
        acc[nt][2] += bb.x + rv2.x; acc[nt][3] += bb.y + rv2.y;
        s1 += acc[nt][0] + acc[nt][1];
        s2 += acc[nt][2] + acc[nt][3];
    }
    s1 += __shfl_xor_sync(0xffffffffu, s1, 1); s1 += __shfl_xor_sync(0xffffffffu, s1, 2);
    s2 += __shfl_xor_sync(0xffffffffu, s2, 1); s2 += __shfl_xor_sync(0xffffffffu, s2, 2);
    float m1 = s1 * (1.f / 128.f), m2 = s2 * (1.f / 128.f);
    float v1 = 0.f, v2 = 0.f;
#pragma unroll
    for (int nt = 0; nt < 16; nt++) {
        float d0 = acc[nt][0] - m1, d1 = acc[nt][1] - m1;
        float d2 = acc[nt][2] - m2, d3 = acc[nt][3] - m2;
        v1 += d0 * d0 + d1 * d1;
        v2 += d2 * d2 + d3 * d3;
    }
    v1 += __shfl_xor_sync(0xffffffffu, v1, 1); v1 += __shfl_xor_sync(0xffffffffu, v1, 2);
    v2 += __shfl_xor_sync(0xffffffffu, v2, 1); v2 += __shfl_xor_sync(0xffffffffu, v2, 2);
    float rr1 = rsqrtf(v1 * (1.f / 128.f) + 1e-8f);
    float rr2 = rsqrtf(v2 * (1.f / 128.f) + 1e-8f);
#pragma unroll
    for (int nt = 0; nt < 16; nt++) {
        int col = (nt << 3) + (t << 1);
        float2 gg = *(const float2*)(lng + col);
        float2 be = *(const float2*)(lnb + col);
        if (r1 < N) {
            float2 o = make_float2((acc[nt][0] - m1) * rr1 * gg.x + be.x,
                                   (acc[nt][1] - m1) * rr1 * gg.y + be.y);
            *(float2*)(C + (size_t)r1 * D + col) = o;
        }
        if (r2 < N) {
            float2 o = make_float2((acc[nt][2] - m2) * rr2 * gg.x + be.x,
                                   (acc[nt][3] - m2) * rr2 * gg.y + be.y);
            *(float2*)(C + (size_t)r2 * D + col) = o;
        }
    }
}

// fused Q/K/V: stage H once (K,V), then Qn (Q)
__global__ void __launch_bounds__(256, 1) gemm_qkv(
    const float* __restrict__ H, const float* __restrict__ Qn,
    const float* __restrict__ in_b, int N) {
    extern __shared__ uint32_t sm_u[];
    uint32_t* sB = sm_u;
    uint32_t* sA = sm_u + 16384;
    int tid = threadIdx.x;
    int row0 = blockIdx.x << 7;
    int warp = tid >> 5, lane = tid & 31;
    float acc[16][4];

    stageA(sA, H, row0, N, tid);
    copyB(sB, g_Wfrag + 1 * D * D, tid);     // Wk
    __syncthreads();
    mmaTile(sA, sB, warp, lane, acc);
    epiPlain(acc, in_b + D, nullptr, g_k, row0, warp, lane, N, false);
    __syncthreads();

    copyB(sB, g_Wfrag + 2 * D * D, tid);     // Wv
    __syncthreads();
    mmaTile(sA, sB, warp, lane, acc);
    epiPlain(acc, in_b + 2 * D, nullptr, g_v, row0, warp, lane, N, false);
    __syncthreads();

    stageA(sA, Qn, row0, N, tid);
    copyB(sB, g_Wfrag + 0 * D * D, tid);     // Wq
    __syncthreads();
    mmaTile(sA, sB, warp, lane, acc);
    epiPlain(acc, in_b, nullptr, g_q, row0, warp, lane, N, false);
}

// ---------------- tensor-core flash attention, CTA per session ----------------
__global__ void __launch_bounds__(256, 2) attn_tc(const int* __restrict__ lens) {
    extern __shared__ uint32_t smA[];
    uint32_t* sKf = smA;                       // [2][MAXKT][4][64]
    uint32_t* sVf = smA + 2 * MAXKT * 256;     // [2][MAXKT][4][64]
    int b = blockIdx.x;
    int l = lens[b];
    int start = g_starts[b];
    int nkt = (l + 7) >> 3, nqt = (l + 15) >> 4;
    int tid = threadIdx.x, w = tid >> 5, lane = tid & 31;
    int g = lane >> 2, t = lane & 3;
    const float qscale = 0.17677669529663687f;  // 1/sqrt(32)

    for (int ph = 0; ph < 2; ph++) {
        int h0 = ph * 2;
        if (ph) __syncthreads();
        // stage K,V (2 heads) into fragment layout, tf32
        int tot = 2 * nkt * 256;
        for (int idx = tid; idx < tot; idx += 256) {
            int head = idx / (nkt * 256);
            int rem = idx - head * nkt * 256;
            int j = rem >> 5, c = rem & 31;
            float kvf = 0.f, vvf = 0.f;
            if (j < l) {
                size_t off = (size_t)(start + j) * D + (h0 + head) * 32 + c;
                kvf = g_k[off];
                vvf = g_v[off];
            }
            int jt = j >> 3;
            int base = (head * MAXKT + jt) * 256;
            int fk = base + (c >> 3) * 64 + ((j & 7) << 3) + ((c & 3) << 1) + ((c >> 2) & 1);
            int fv = base + (c >> 3) * 64 + ((c & 7) << 3) + ((j & 3) << 1) + ((j >> 2) & 1);
            sKf[fk] = f2tf32(kvf);
            sVf[fv] = f2tf32(vvf);
        }
        __syncthreads();

        int ntask = 2 * nqt;
        for (int task = w; task < ntask; task += 8) {
            int head = task / nqt;
            int qt = task - head * nqt;
            int h = h0 + head;
            int r0 = qt * 16;
            // load Q A-fragments (4 k-chunks)
            uint32_t qa[4][4];
#pragma unroll
            for (int kc = 0; kc < 4; kc++) {
                int c = kc * 8 + t;
                size_t ro = (size_t)(start + r0 + g) * D + h * 32 + c;
                size_t ro8 = ro + (size_t)8 * D;
                qa[kc][0] = f2tf32(g_q[ro] * qscale);
                qa[kc][1] = f2tf32(g_q[ro8] * qscale);
                qa[kc][2] = f2tf32(g_q[ro + 4] * qscale);
                qa[kc][3] = f2tf32(g_q[ro8 + 4] * qscale);
            }
            float o[4][4];
#pragma unroll
            for (int nc = 0; nc < 4; nc++)
#pragma unroll
                for (int m = 0; m < 4; m++) o[nc][m] = 0.f;
            float mr0 = -3.0e38f, mr1 = -3.0e38f, sr0 = 0.f, sr1 = 0.f;
            const uint32_t* Kb = sKf + head * MAXKT * 256;
            const uint32_t* Vb = sVf + head * MAXKT * 256;
            int srcidx = (g << 2) + (t >> 1);
            bool odd = t & 1;

            for (int kt = 0; kt < nkt; kt++) {
                float s0 = 0.f, s1 = 0.f, s2 = 0.f, s3 = 0.f;
                const uint32_t* kp = Kb + kt * 256 + (lane << 1);
#pragma unroll
                for (int kc = 0; kc < 4; kc++) {
                    uint2 bb = *(const uint2*)(kp + (kc << 6));
                    MMA_TF32(s0, s1, s2, s3, qa[kc][0], qa[kc][1], qa[kc][2], qa[kc][3], bb.x, bb.y);
                }
                int col0 = kt * 8 + 2 * t;
                if (col0 >= l)     { s0 = -3.0e38f; s2 = -3.0e38f; }
                if (col0 + 1 >= l) { s1 = -3.0e38f; s3 = -3.0e38f; }
                float tm0 = fmaxf(s0, s1), tm1 = fmaxf(s2, s3);
                tm0 = fmaxf(tm0, __shfl_xor_sync(0xffffffffu, tm0, 1));
                tm0 = fmaxf(tm0, __shfl_xor_sync(0xffffffffu, tm0, 2));
                tm1 = fmaxf(tm1, __shfl_xor_sync(0xffffffffu, tm1, 1));
                tm1 = fmaxf(tm1, __shfl_xor_sync(0xffffffffu, tm1, 2));
                float mn0 = fmaxf(mr0, tm0), mn1 = fmaxf(mr1, tm1);
                float al0 = __expf(mr0 - mn0), al1 = __expf(mr1 - mn1);
                mr0 = mn0; mr1 = mn1;
                float p0 = __expf(s0 - mn0), p1 = __expf(s1 - mn0);
                float p2 = __expf(s2 - mn1), p3 = __expf(s3 - mn1);
                float ts0 = p0 + p1, ts1 = p2 + p3;
                ts0 += __shfl_xor_sync(0xffffffffu, ts0, 1);
                ts0 += __shfl_xor_sync(0xffffffffu, ts0, 2);
                ts1 += __shfl_xor_sync(0xffffffffu, ts1, 1);
                ts1 += __shfl_xor_sync(0xffffffffu, ts1, 2);
                sr0 = sr0 * al0 + ts0;
                sr1 = sr1 * al1 + ts1;
#pragma unroll
                for (int nc = 0; nc < 4; nc++) {
                    o[nc][0] *= al0; o[nc][1] *= al1;
                    o[nc][2] *= al0; o[nc][3] *= al1;
                }
                // relayout P (C-frag) -> A-frag
                float h0a = __shfl_sync(0xffffffffu, p0, srcidx);
                float h1a = __shfl_sync(0xffffffffu, p1, srcidx);
                float h0b = __shfl_sync(0xffffffffu, p0, srcidx + 2);
                float h1b = __shfl_sync(0xffffffffu, p1, srcidx + 2);
                float h2a = __shfl_sync(0xffffffffu, p2, srcidx);
                float h3a = __shfl_sync(0xffffffffu, p3, srcidx);
                float h2b = __shfl_sync(0xffffffffu, p2, srcidx + 2);
                float h3b = __shfl_sync(0xffffffffu, p3, srcidx + 2);
                uint32_t pa0 = f2tf32(odd ? h1a : h0a);
                uint32_t pa1 = f2tf32(odd ? h3a : h2a);
                uint32_t pa2 = f2tf32(odd ? h1b : h0b);
                uint32_t pa3 = f2tf32(odd ? h3b : h2b);
                const uint32_t* vp = Vb + kt * 256 + (lane << 1);
#pragma unroll
                for (int nc = 0; nc < 4; nc++) {
                    uint2 vb = *(const uint2*)(vp + (nc << 6));
                    MMA_TF32(o[nc][0], o[nc][1], o[nc][2], o[nc][3],
                             pa0, pa1, pa2, pa3, vb.x, vb.y);
                }
            }
            float inv0 = 1.f / sr0, inv1 = 1.f / sr1;
            int rr = r0 + g;
#pragma unroll
            for (int nc = 0; nc < 4; nc++) {
                int col = h * 32 + nc * 8 + 2 * t;
                if (rr < l)
                    *(float2*)(g_ctx + (size_t)(start + rr) * D + col) =
                        make_float2(o[nc][0] * inv0, o[nc][1] * inv0);
                if (rr + 8 < l)
                    *(float2*)(g_ctx + (size_t)(start + rr + 8) * D + col) =
                        make_float2(o[nc][2] * inv1, o[nc][3] * inv1);
            }
        }
    }
}

// ---------------- masked mean pool ----------------
__global__ void k_pool(const int* __restrict__ lens, float* __restrict__ out) {
    int b = (blockIdx.x * blockDim.x + threadIdx.x) >> 5;
    int lane = threadIdx.x & 31;
    if (b >= BATCH) return;
    int l = lens[b], s = g_starts[b];
    float4 acc = make_float4(0.f, 0.f, 0.f, 0.f);
    for (int p = 0; p < l; p++) {
        float4 v = ((const float4*)g_fin)[(size_t)(s + p) * 32 + lane];
        acc.x += v.x; acc.y += v.y; acc.z += v.z; acc.w += v.w;
    }
    float iv = 1.f / (float)l;
    ((float4*)out)[b * 32 + lane] =
        make_float4(acc.x * iv, acc.y * iv, acc.z * iv, acc.w * iv);
}

// ---------------- launch ----------------
extern "C" void kernel_launch(void* const* d_in, const int* in_sizes, int n_in,
                              void* d_out, int out_size) {
    const float* POI   = (const float*)d_in[0];
    const float* ddis  = (const float*)d_in[1];
    const float* attW  = (const float*)d_in[2];
    const float* a_src = (const float*)d_in[3];
    const float* a_dst = (const float*)d_in[4];
    const float* in_w  = (const float*)d_in[5];
    const float* in_b  = (const float*)d_in[6];
    const float* out_w = (const float*)d_in[7];
    const float* out_b = (const float*)d_in[8];
    const float* ln1g  = (const float*)d_in[9];
    const float* ln1b  = (const float*)d_in[10];
    const float* ln2g  = (const float*)d_in[11];
    const float* ln2b  = (const float*)d_in[12];
    const float* w1    = (const float*)d_in[13];
    const float* b1    = (const float*)d_in[14];
    const float* w2    = (const float*)d_in[15];
    const float* b2    = (const float*)d_in[16];
    const int* sess  = (const int*)d_in[17];
    const int* edist = (const int*)d_in[18];
    const int* bids  = (const int*)d_in[20];
    const int* npos  = (const int*)d_in[21];
    const int* lens  = (const int*)d_in[22];
    int N = in_sizes[17];
    int V = in_sizes[0] / D;

    float *pH, *pQn, *pq, *pctx, *po2, *pf1, *pfin;
    uint32_t* pWf;
    cudaGetSymbolAddress((void**)&pH, g_H);
    cudaGetSymbolAddress((void**)&pQn, g_Qn);
    cudaGetSymbolAddress((void**)&pq, g_q);
    cudaGetSymbolAddress((void**)&pctx, g_ctx);
    cudaGetSymbolAddress((void**)&po2, g_o2);
    cudaGetSymbolAddress((void**)&pf1, g_f1);
    cudaGetSymbolAddress((void**)&pfin, g_fin);
    cudaGetSymbolAddress((void**)&pWf, g_Wfrag);

    size_t gsh = (size_t)(16384 + 128 * 132) * sizeof(uint32_t);  // 130 KB
    cudaFuncSetAttribute(gemm_fused, cudaFuncAttributeMaxDynamicSharedMemorySize, (int)gsh);
    cudaFuncSetAttribute(gemm_qkv, cudaFuncAttributeMaxDynamicSharedMemorySize, (int)gsh);
    size_t ash = (size_t)(4 * MAXKT * 256) * sizeof(uint32_t);    // 80 KB
    cudaFuncSetAttribute(attn_tc, cudaFuncAttributeMaxDynamicSharedMemorySize, (int)ash);

    int pv_blocks = (V + 7) / 8;
    k_cvec<<<1, 128>>>(attW, a_src, a_dst);
    k_pre2<<<5 + 384 + pv_blocks, 256>>>(ddis, lens, in_w, out_w, w1, w2, POI, V);
    k_node<<<(N + 7) / 8, 256>>>(POI, sess, edist, bids, npos, lens, ln1g, ln1b, N);

    int gb = (N + 127) / 128;
    gemm_qkv<<<gb, 256, gsh>>>(pH, pQn, in_b, N);
    attn_tc<<<BATCH, 256, ash>>>(lens);
    // out-proj + residual(Qn) + LN2 fused
    gemm_fused<<<gb, 256, gsh>>>(pctx, pWf + 3 * D * D, out_b, pQn, ln2g, ln2b, po2, N, 3);
    // FFN
    gemm_fused<<<gb, 256, gsh>>>(po2, pWf + 4 * D * D, b1, nullptr, nullptr, nullptr, pf1, N, 1);
    gemm_fused<<<gb, 256, gsh>>>(pf1, pWf + 5 * D * D, b2, po2, nullptr, nullptr, pfin, N, 2);
    k_pool<<<(BATCH + 7) / 8, 256>>>(lens, (float*)d_out);
}

// round 5
// speedup vs baseline: 2.5874x; 1.0337x over previous
#include <cuda_runtime.h>
#include <math.h>
#include <stdint.h>

#define D 128
#define BATCH 1024
#define MAXLEN 160
#define NMAX 114000
#define VMAX 50048
#define MAXKT 20   // max key tiles of 8 (160/8)

// ---------------- device scratch ----------------
__device__ __align__(16) float g_csrc[D];
__device__ __align__(16) float g_cdst[D];
__device__ __align__(16) float g_ddot[512];
__device__ __align__(16) float g_pvs[VMAX];
__device__ __align__(16) float g_pvd[VMAX];
__device__ int   g_starts[BATCH];
__device__ __align__(16) uint32_t g_Wfrag[6 * D * D];   // tf32 fragment-ordered weights: q,k,v,o,f1,f2
__device__ __align__(16) float g_H  [(size_t)NMAX * D];
__device__ __align__(16) float g_Qn [(size_t)NMAX * D];
__device__ __align__(16) float g_q  [(size_t)NMAX * D];
__device__ __align__(16) float g_k  [(size_t)NMAX * D];
__device__ __align__(16) float g_v  [(size_t)NMAX * D];
__device__ __align__(16) float g_ctx[(size_t)NMAX * D];
__device__ __align__(16) float g_o2 [(size_t)NMAX * D];
__device__ __align__(16) float g_f1 [(size_t)NMAX * D];
__device__ __align__(16) float g_fin[(size_t)NMAX * D];

__device__ __forceinline__ float wsum(float v) {
#pragma unroll
    for (int o = 16; o; o >>= 1) v += __shfl_xor_sync(0xffffffffu, v, o);
    return v;
}
__device__ __forceinline__ uint32_t f2tf32(float f) {
    uint32_t u;
    asm("cvt.rna.tf32.f32 %0, %1;" : "=r"(u) : "f"(f));
    return u;
}
#define MMA_TF32(c0,c1,c2,c3,a0,a1,a2,a3,b0,b1) \
    asm volatile("mma.sync.aligned.m16n8k8.row.col.f32.tf32.tf32.f32 " \
                 "{%0,%1,%2,%3}, {%4,%5,%6,%7}, {%8,%9}, {%0,%1,%2,%3};" \
                 : "+f"(c0), "+f"(c1), "+f"(c2), "+f"(c3) \
                 : "r"(a0), "r"(a1), "r"(a2), "r"(a3), "r"(b0), "r"(b1))

// shared-memory sizes for GEMM kernels (in u32 words)
#define SB_WORDS 16384           // B fragments 128x128
#define SA_WORDS (64 * 132)      // A tile 64 rows, pad 132
#define RED_WORDS 512            // LN partials: 64 rows x 4 bands x {sum,sq}
#define GEMM_SMEM_BYTES ((SB_WORDS + SA_WORDS + RED_WORDS) * 4)

// ---------------- precompute: c vectors ----------------
__global__ void k_cvec(const float* __restrict__ W, const float* __restrict__ as,
                       const float* __restrict__ ad) {
    int k = threadIdx.x;
    float s = 0.f, d = 0.f;
    for (int j = 0; j < D; j++) {
        float w = W[j * D + k];
        s += as[j] * w;
        d += ad[j] * w;
    }
    g_csrc[k] = s;
    g_cdst[k] = d;
}

// ---------------- merged precompute 2: ddot, starts, weight frags, pv ----------------
__global__ void k_pre2(const float* __restrict__ dd, const int* __restrict__ lens,
                       const float* __restrict__ in_w, const float* __restrict__ out_w,
                       const float* __restrict__ w1, const float* __restrict__ w2,
                       const float* __restrict__ POI, int V) {
    int blk = blockIdx.x;
    int tid = threadIdx.x;
    if (blk < 4) {
        int t = blk * 128 + (tid & 127);
        if (tid < 128) {
            float s = 0.f;
            for (int k = 0; k < D; k++) s += dd[t * D + k] * g_csrc[k];
            g_ddot[t] = s;
        }
    } else if (blk == 4) {
        __shared__ int sl[BATCH];
        for (int i = tid; i < BATCH; i += 256) sl[i] = lens[i];
        __syncthreads();
        if (tid == 0) {
            int s = 0;
            for (int i = 0; i < BATCH; i++) { int t = sl[i]; sl[i] = s; s += t; }
        }
        __syncthreads();
        for (int i = tid; i < BATCH; i += 256) g_starts[i] = sl[i];
    } else if (blk < 5 + 6 * 64) {
        int bb = blk - 5;
        int m = bb >> 6;
        int e = ((bb & 63) << 8) + tid;
        int k = e >> 7, n = e & 127;
        const float* src;
        if (m < 3) src = in_w + m * D * D;
        else if (m == 3) src = out_w;
        else if (m == 4) src = w1;
        else src = w2;
        float v = src[n * D + k];
        int fo = (((k >> 3) << 4) + (n >> 3)) * 64 + ((n & 7) << 3) + ((k & 3) << 1) + ((k >> 2) & 1);
        g_Wfrag[m * D * D + fo] = f2tf32(v);
    } else {
        int v = (blk - (5 + 384)) * 8 + (tid >> 5);
        int lane = tid & 31;
        if (v >= V) return;
        float4 x  = ((const float4*)POI)[(size_t)v * 32 + lane];
        float4 cs = ((const float4*)g_csrc)[lane];
        float4 cd = ((const float4*)g_cdst)[lane];
        float ps = wsum(x.x * cs.x + x.y * cs.y + x.z * cs.z + x.w * cs.w);
        float pd = wsum(x.x * cd.x + x.y * cd.y + x.z * cd.z + x.w * cd.w);
        if (lane == 0) { g_pvs[v] = ps; g_pvd[v] = pd; }
    }
}

// ---------------- fused GCN (2-way softmax) + LayerNorm1 ----------------
__global__ void k_node(const float* __restrict__ POI, const int* __restrict__ sess,
                       const int* __restrict__ edist, const int* __restrict__ bids,
                       const int* __restrict__ npos, const int* __restrict__ lens,
                       const float* __restrict__ g1, const float* __restrict__ b1v, int N) {
    int n = (blockIdx.x * blockDim.x + threadIdx.x) >> 5;
    int lane = threadIdx.x & 31;
    if (n >= N) return;
    int b = bids[n], p = npos[n], l = lens[b];
    int vi = sess[n];
    bool hasF = (p > 0);
    bool hasB = (p < l - 1);
    float lf = hasF ? (g_pvs[vi] + g_ddot[edist[n - b - 1]]) : -3.0e38f;
    float lb = hasB ? g_pvd[vi] : -3.0e38f;
    float m = fmaxf(lf, lb);
    float ef = hasF ? __expf(lf - m) : 0.f;
    float eb = hasB ? __expf(lb - m) : 0.f;
    float inv = 1.f / (ef + eb + 1e-16f);

    float4 hv = make_float4(0.f, 0.f, 0.f, 0.f);
    if (hasF) {
        float4 xm = ((const float4*)POI)[(size_t)sess[n - 1] * 32 + lane];
        hv.x = ef * xm.x; hv.y = ef * xm.y; hv.z = ef * xm.z; hv.w = ef * xm.w;
    }
    if (hasB) {
        float4 xp = ((const float4*)POI)[(size_t)sess[n + 1] * 32 + lane];
        hv.x += eb * xp.x; hv.y += eb * xp.y; hv.z += eb * xp.z; hv.w += eb * xp.w;
    }
    hv.x *= inv; hv.y *= inv; hv.z *= inv; hv.w *= inv;
    ((float4*)g_H)[(size_t)n * 32 + lane] = hv;

    float mean = wsum(hv.x + hv.y + hv.z + hv.w) * (1.f / 128.f);
    float4 dx = make_float4(hv.x - mean, hv.y - mean, hv.z - mean, hv.w - mean);
    float var = wsum(dx.x * dx.x + dx.y * dx.y + dx.z * dx.z + dx.w * dx.w) * (1.f / 128.f);
    float r = rsqrtf(var + 1e-8f);
    float4 gg = ((const float4*)g1)[lane];
    float4 bb = ((const float4*)b1v)[lane];
    float4 qn = make_float4(dx.x * r * gg.x + bb.x, dx.y * r * gg.y + bb.y,
                            dx.z * r * gg.z + bb.z, dx.w * r * gg.w + bb.w);
    ((float4*)g_Qn)[(size_t)n * 32 + lane] = qn;
}

// ---------------- GEMM building blocks (64-row tiles, 2 CTAs/SM) ----------------
__device__ __forceinline__ void copyB(uint32_t* sB, const uint32_t* __restrict__ Bf, int tid) {
#pragma unroll
    for (int i = 0; i < 16; i++)
        ((uint4*)sB)[tid + 256 * i] = ((const uint4*)Bf)[tid + 256 * i];
}

__device__ __forceinline__ void stageA64(uint32_t* sA, const float* __restrict__ A,
                                         int row0, int N, int tid) {
#pragma unroll
    for (int i = 0; i < 8; i++) {
        int idx = tid + 256 * i;            // 0..2047 -> 64 rows x 32 float4
        int r = idx >> 5, c4 = idx & 31;
        float4 v = make_float4(0.f, 0.f, 0.f, 0.f);
        if (row0 + r < N) v = ((const float4*)A)[((size_t)(row0 + r) << 5) + c4];
        uint4 p;
        p.x = f2tf32(v.x); p.y = f2tf32(v.y); p.z = f2tf32(v.z); p.w = f2tf32(v.w);
        ((uint4*)sA)[r * 33 + c4] = p;
    }
}

// warp layout: wr = warp>>2 (2 row bands of 32), wc = warp&3 (4 col bands of 32)
// acc[mg][nt][4]: mg in {0,1} -> rows wr*32+mg*16..+15; nt in 0..3 -> cols wc*32+nt*8..+7
__device__ __forceinline__ void mmaTile64(const uint32_t* sA, const uint32_t* sB,
                                          int warp, int lane, float acc[2][4][4]) {
    int g = lane >> 2, t = lane & 3;
    int wr = warp >> 2, wc = warp & 3;
#pragma unroll
    for (int mg = 0; mg < 2; mg++)
#pragma unroll
        for (int nt = 0; nt < 4; nt++)
#pragma unroll
            for (int m = 0; m < 4; m++) acc[mg][nt][m] = 0.f;
    const uint32_t* sAw = sA + (wr * 32) * 132;
    const uint32_t* sBw = sB + (wc * 4) * 64 + (lane << 1);
#pragma unroll
    for (int ks = 0; ks < 16; ks++) {
        int kb = ks * 8 + t;
        uint32_t a[2][4];
#pragma unroll
        for (int mg = 0; mg < 2; mg++) {
            const uint32_t* ap = sAw + (mg * 16 + g) * 132 + kb;
            a[mg][0] = ap[0];
            a[mg][1] = ap[8 * 132];
            a[mg][2] = ap[4];
            a[mg][3] = ap[8 * 132 + 4];
        }
        const uint32_t* bp = sBw + (ks << 10);
#pragma unroll
        for (int nt = 0; nt < 4; nt++) {
            uint2 b = *(const uint2*)(bp + (nt << 6));
#pragma unroll
            for (int mg = 0; mg < 2; mg++)
                MMA_TF32(acc[mg][nt][0], acc[mg][nt][1], acc[mg][nt][2], acc[mg][nt][3],
                         a[mg][0], a[mg][1], a[mg][2], a[mg][3], b.x, b.y);
        }
    }
}

__device__ __forceinline__ void epi64(float acc[2][4][4], const float* __restrict__ bias,
                                      const float* __restrict__ res, float* __restrict__ C,
                                      int row0, int warp, int lane, int N, bool relu) {
    int g = lane >> 2, t = lane & 3;
    int wr = warp >> 2, wc = warp & 3;
#pragma unroll
    for (int mg = 0; mg < 2; mg++) {
        int r1 = row0 + wr * 32 + mg * 16 + g;
        int r2 = r1 + 8;
#pragma unroll
        for (int nt = 0; nt < 4; nt++) {
            int col = wc * 32 + (nt << 3) + (t << 1);
            float2 bb = *(const float2*)(bias + col);
            float2 o1 = make_float2(acc[mg][nt][0] + bb.x, acc[mg][nt][1] + bb.y);
            float2 o2 = make_float2(acc[mg][nt][2] + bb.x, acc[mg][nt][3] + bb.y);
            if (relu) {
                o1.x = fmaxf(o1.x, 0.f); o1.y = fmaxf(o1.y, 0.f);
                o2.x = fmaxf(o2.x, 0.f); o2.y = fmaxf(o2.y, 0.f);
            }
            if (r1 < N) {
                if (res) { float2 rv = *(const float2*)(res + (size_t)r1 * D + col); o1.x += rv.x; o1.y += rv.y; }
                *(float2*)(C + (size_t)r1 * D + col) = o1;
            }
            if (r2 < N) {
                if (res) { float2 rv = *(const float2*)(res + (size_t)r2 * D + col); o2.x += rv.x; o2.y += rv.y; }
                *(float2*)(C + (size_t)r2 * D + col) = o2;
            }
        }
    }
}

// generic GEMM: mode 0=bias, 1=bias+relu, 2=bias+res, 3=bias+res+LayerNorm2
__global__ void __launch_bounds__(256, 2) gemm_fused(
    const float* __restrict__ A, const uint32_t* __restrict__ Bfrag,
    const float* __restrict__ bias, const float* __restrict__ res,
    const float* __restrict__ lng, const float* __restrict__ lnb,
    float* __restrict__ C, int N, int mode) {
    extern __shared__ uint32_t sm_u[];
    uint32_t* sB = sm_u;
    uint32_t* sA = sm_u + SB_WORDS;
    float* red = (float*)(sm_u + SB_WORDS + SA_WORDS);   // [64][4] sum, [64][4] sq
    int tid = threadIdx.x;
    copyB(sB, Bfrag, tid);
    int row0 = blockIdx.x << 6;
    stageA64(sA, A, row0, N, tid);
    __syncthreads();

    int warp = tid >> 5, lane = tid & 31;
    float acc[2][4][4];
    mmaTile64(sA, sB, warp, lane, acc);

    if (mode != 3) {
        epi64(acc, bias, res, C, row0, warp, lane, N, mode == 1);
        return;
    }
    // mode 3: bias + residual + LayerNorm2 (cross-warp row reduction via smem)
    int g = lane >> 2, t = lane & 3;
    int wr = warp >> 2, wc = warp & 3;
#pragma unroll
    for (int mg = 0; mg < 2; mg++) {
        int r1 = row0 + wr * 32 + mg * 16 + g;
        int r2 = r1 + 8;
        float s1 = 0.f, s2 = 0.f, q1 = 0.f, q2 = 0.f;
#pragma unroll
        for (int nt = 0; nt < 4; nt++) {
            int col = wc * 32 + (nt << 3) + (t << 1);
            float2 bb = *(const float2*)(bias + col);
            float2 rv1 = make_float2(0.f, 0.f), rv2 = make_float2(0.f, 0.f);
            if (r1 < N) rv1 = *(const float2*)(res + (size_t)r1 * D + col);
            if (r2 < N) rv2 = *(const float2*)(res + (size_t)r2 * D + col);
            acc[mg][nt][0] += bb.x + rv1.x; acc[mg][nt][1] += bb.y + rv1.y;
            acc[mg][nt][2] += bb.x + rv2.x; acc[mg][nt][3] += bb.y + rv2.y;
            s1 += acc[mg][nt][0] + acc[mg][nt][1];
            s2 += acc[mg][nt][2] + acc[mg][nt][3];
            q1 += acc[mg][nt][0] * acc[mg][nt][0] + acc[mg][nt][1] * acc[mg][nt][1];
            q2 += acc[mg][nt][2] * acc[mg][nt][2] + acc[mg][nt][3] * acc[mg][nt][3];
        }
        // reduce across the 4 t-lanes (same row)
        s1 += __shfl_xor_sync(0xffffffffu, s1, 1); s1 += __shfl_xor_sync(0xffffffffu, s1, 2);
        s2 += __shfl_xor_sync(0xffffffffu, s2, 1); s2 += __shfl_xor_sync(0xffffffffu, s2, 2);
        q1 += __shfl_xor_sync(0xffffffffu, q1, 1); q1 += __shfl_xor_sync(0xffffffffu, q1, 2);
        q2 += __shfl_xor_sync(0xffffffffu, q2, 1); q2 += __shfl_xor_sync(0xffffffffu, q2, 2);
        if (t == 0) {
            int lr1 = wr * 32 + mg * 16 + g;
            red[lr1 * 4 + wc] = s1;
            red[(lr1 + 8) * 4 + wc] = s2;
            red[256 + lr1 * 4 + wc] = q1;
            red[256 + (lr1 + 8) * 4 + wc] = q2;
        }
    }
    __syncthreads();
#pragma unroll
    for (int mg = 0; mg < 2; mg++) {
        int lr1 = wr * 32 + mg * 16 + g;
        int r1 = row0 + lr1, r2 = r1 + 8;
        float s1 = red[lr1 * 4] + red[lr1 * 4 + 1] + red[lr1 * 4 + 2] + red[lr1 * 4 + 3];
        float s2 = red[(lr1 + 8) * 4] + red[(lr1 + 8) * 4 + 1] + red[(lr1 + 8) * 4 + 2] + red[(lr1 + 8) * 4 + 3];
        float q1 = red[256 + lr1 * 4] + red[256 + lr1 * 4 + 1] + red[256 + lr1 * 4 + 2] + red[256 + lr1 * 4 + 3];
        float q2 = red[256 + (lr1 + 8) * 4] + red[256 + (lr1 + 8) * 4 + 1] + red[256 + (lr1 + 8) * 4 + 2] + red[256 + (lr1 + 8) * 4 + 3];
        float m1 = s1 * (1.f / 128.f), m2 = s2 * (1.f / 128.f);
        float v1 = q1 * (1.f / 128.f) - m1 * m1;
        float v2 = q2 * (1.f / 128.f) - m2 * m2;
        float rr1 = rsqrtf(fmaxf(v1, 0.f) + 1e-8f);
        float rr2 = rsqrtf(fmaxf(v2, 0.f) + 1e-8f);
#pragma unroll
        for (int nt = 0; nt < 4; nt++) {
            int col = wc * 32 + (nt << 3) + (t << 1);
            float2 gg = *(const float2*)(lng + col);
            float2 be = *(const float2*)(lnb + col);
            if (r1 < N) {
                float2 o = make_float2((acc[mg][nt][0] - m1) * rr1 * gg.x + be.x,
                                       (acc[mg][nt][1] - m1) * rr1 * gg.y + be.y);
                *(float2*)(C + (size_t)r1 * D + col) = o;
            }
            if (r2 < N) {
                float2 o = make_float2((acc[mg][nt][2] - m2) * rr2 * gg.x + be.x,
                                       (acc[mg][nt][3] - m2) * rr2 * gg.y + be.y);
                *(float2*)(C + (size_t)r2 * D + col) = o;
            }
        }
    }
}

// fused Q/K/V: stage H once (K,V), then Qn (Q)
__global__ void __launch_bounds__(256, 2) gemm_qkv(
    const float* __restrict__ H, const float* __restrict__ Qn,
    const float* __restrict__ in_b, int N) {
    extern __shared__ uint32_t sm_u[];
    uint32_t* sB = sm_u;
    uint32_t* sA = sm_u + SB_WORDS;
    int tid = threadIdx.x;
    int row0 = blockIdx.x << 6;
    int warp = tid >> 5, lane = tid & 31;
    float acc[2][4][4];

    stageA64(sA, H, row0, N, tid);
    copyB(sB, g_Wfrag + 1 * D * D, tid);     // Wk
    __syncthreads();
    mmaTile64(sA, sB, warp, lane, acc);
    epi64(acc, in_b + D, nullptr, g_k, row0, warp, lane, N, false);
    __syncthreads();

    copyB(sB, g_Wfrag + 2 * D * D, tid);     // Wv
    __syncthreads();
    mmaTile64(sA, sB, warp, lane, acc);
    epi64(acc, in_b + 2 * D, nullptr, g_v, row0, warp, lane, N, false);
    __syncthreads();

    stageA64(sA, Qn, row0, N, tid);
    copyB(sB, g_Wfrag + 0 * D * D, tid);     // Wq
    __syncthreads();
    mmaTile64(sA, sB, warp, lane, acc);
    epi64(acc, in_b, nullptr, g_q, row0, warp, lane, N, false);
}

// ---------------- tensor-core flash attention, CTA per (session, head) ----------------
__global__ void __launch_bounds__(128) attn_tc(const int* __restrict__ lens) {
    extern __shared__ uint32_t smA[];
    uint32_t* sKf = smA;                       // [MAXKT][256]
    uint32_t* sVf = smA + MAXKT * 256;
    int b = blockIdx.x, h = blockIdx.y;
    int l = lens[b];
    int start = g_starts[b];
    int nkt = (l + 7) >> 3, nqt = (l + 15) >> 4;
    int tid = threadIdx.x, w = tid >> 5, lane = tid & 31;
    int g = lane >> 2, t = lane & 3;
    const float qscale = 0.17677669529663687f;  // 1/sqrt(32)

    // stage K,V for this head into fragment layout, tf32
    int tot = nkt * 256;
    for (int idx = tid; idx < tot; idx += 128) {
        int j = idx >> 5, c = idx & 31;
        float kvf = 0.f, vvf = 0.f;
        if (j < l) {
            size_t off = (size_t)(start + j) * D + h * 32 + c;
            kvf = g_k[off];
            vvf = g_v[off];
        }
        int base = (j >> 3) * 256;
        int fk = base + (c >> 3) * 64 + ((j & 7) << 3) + ((c & 3) << 1) + ((c >> 2) & 1);
        int fv = base + (c >> 3) * 64 + ((c & 7) << 3) + ((j & 3) << 1) + ((j >> 2) & 1);
        sKf[fk] = f2tf32(kvf);
        sVf[fv] = f2tf32(vvf);
    }
    __syncthreads();

    int srcidx = (g << 2) + (t >> 1);
    bool odd = t & 1;

    for (int qt = w; qt < nqt; qt += 4) {
        int r0 = qt * 16;
        uint32_t qa[4][4];
#pragma unroll
        for (int kc = 0; kc < 4; kc++) {
            int c = kc * 8 + t;
            size_t ro = (size_t)(start + r0 + g) * D + h * 32 + c;
            size_t ro8 = ro + (size_t)8 * D;
            qa[kc][0] = f2tf32(g_q[ro] * qscale);
            qa[kc][1] = f2tf32(g_q[ro8] * qscale);
            qa[kc][2] = f2tf32(g_q[ro + 4] * qscale);
            qa[kc][3] = f2tf32(g_q[ro8 + 4] * qscale);
        }
        float o[4][4];
#pragma unroll
        for (int nc = 0; nc < 4; nc++)
#pragma unroll
            for (int m = 0; m < 4; m++) o[nc][m] = 0.f;
        float mr0 = -3.0e38f, mr1 = -3.0e38f, sr0 = 0.f, sr1 = 0.f;

        for (int kt = 0; kt < nkt; kt++) {
            float s0 = 0.f, s1 = 0.f, s2 = 0.f, s3 = 0.f;
            const uint32_t* kp = sKf + kt * 256 + (lane << 1);
#pragma unroll
            for (int kc = 0; kc < 4; kc++) {
                uint2 bb = *(const uint2*)(kp + (kc << 6));
                MMA_TF32(s0, s1, s2, s3, qa[kc][0], qa[kc][1], qa[kc][2], qa[kc][3], bb.x, bb.y);
            }
            int col0 = kt * 8 + 2 * t;
            if (col0 >= l)     { s0 = -3.0e38f; s2 = -3.0e38f; }
            if (col0 + 1 >= l) { s1 = -3.0e38f; s3 = -3.0e38f; }
            float tm0 = fmaxf(s0, s1), tm1 = fmaxf(s2, s3);
            tm0 = fmaxf(tm0, __shfl_xor_sync(0xffffffffu, tm0, 1));
            tm0 = fmaxf(tm0, __shfl_xor_sync(0xffffffffu, tm0, 2));
            tm1 = fmaxf(tm1, __shfl_xor_sync(0xffffffffu, tm1, 1));
            tm1 = fmaxf(tm1, __shfl_xor_sync(0xffffffffu, tm1, 2));
            float mn0 = fmaxf(mr0, tm0), mn1 = fmaxf(mr1, tm1);
            float al0 = __expf(mr0 - mn0), al1 = __expf(mr1 - mn1);
            mr0 = mn0; mr1 = mn1;
            float p0 = __expf(s0 - mn0), p1 = __expf(s1 - mn0);
            float p2 = __expf(s2 - mn1), p3 = __expf(s3 - mn1);
            float ts0 = p0 + p1, ts1 = p2 + p3;
            ts0 += __shfl_xor_sync(0xffffffffu, ts0, 1);
            ts0 += __shfl_xor_sync(0xffffffffu, ts0, 2);
            ts1 += __shfl_xor_sync(0xffffffffu, ts1, 1);
            ts1 += __shfl_xor_sync(0xffffffffu, ts1, 2);
            sr0 = sr0 * al0 + ts0;
            sr1 = sr1 * al1 + ts1;
#pragma unroll
            for (int nc = 0; nc < 4; nc++) {
                o[nc][0] *= al0; o[nc][1] *= al1;
                o[nc][2] *= al0; o[nc][3] *= al1;
            }
            float h0a = __shfl_sync(0xffffffffu, p0, srcidx);
            float h1a = __shfl_sync(0xffffffffu, p1, srcidx);
            float h0b = __shfl_sync(0xffffffffu, p0, srcidx + 2);
            float h1b = __shfl_sync(0xffffffffu, p1, srcidx + 2);
            float h2a = __shfl_sync(0xffffffffu, p2, srcidx);
            float h3a = __shfl_sync(0xffffffffu, p3, srcidx);
            float h2b = __shfl_sync(0xffffffffu, p2, srcidx + 2);
            float h3b = __shfl_sync(0xffffffffu, p3, srcidx + 2);
            uint32_t pa0 = f2tf32(odd ? h1a : h0a);
            uint32_t pa1 = f2tf32(odd ? h3a : h2a);
            uint32_t pa2 = f2tf32(odd ? h1b : h0b);
            uint32_t pa3 = f2tf32(odd ? h3b : h2b);
            const uint32_t* vp = sVf + kt * 256 + (lane << 1);
#pragma unroll
            for (int nc = 0; nc < 4; nc++) {
                uint2 vb = *(const uint2*)(vp + (nc << 6));
                MMA_TF32(o[nc][0], o[nc][1], o[nc][2], o[nc][3],
                         pa0, pa1, pa2, pa3, vb.x, vb.y);
            }
        }
        float inv0 = 1.f / sr0, inv1 = 1.f / sr1;
        int rr = r0 + g;
#pragma unroll
        for (int nc = 0; nc < 4; nc++) {
            int col = h * 32 + nc * 8 + 2 * t;
            if (rr < l)
                *(float2*)(g_ctx + (size_t)(start + rr) * D + col) =
                    make_float2(o[nc][0] * inv0, o[nc][1] * inv0);
            if (rr + 8 < l)
                *(float2*)(g_ctx + (size_t)(start + rr + 8) * D + col) =
                    make_float2(o[nc][2] * inv1, o[nc][3] * inv1);
        }
    }
}

// ---------------- masked mean pool ----------------
__global__ void k_pool(const int* __restrict__ lens, float* __restrict__ out) {
    int b = (blockIdx.x * blockDim.x + threadIdx.x) >> 5;
    int lane = threadIdx.x & 31;
    if (b >= BATCH) return;
    int l = lens[b], s = g_starts[b];
    float4 acc = make_float4(0.f, 0.f, 0.f, 0.f);
    for (int p = 0; p < l; p++) {
        float4 v = ((const float4*)g_fin)[(size_t)(s + p) * 32 + lane];
        acc.x += v.x; acc.y += v.y; acc.z += v.z; acc.w += v.w;
    }
    float iv = 1.f / (float)l;
    ((float4*)out)[b * 32 + lane] =
        make_float4(acc.x * iv, acc.y * iv, acc.z * iv, acc.w * iv);
}

// ---------------- launch ----------------
extern "C" void kernel_launch(void* const* d_in, const int* in_sizes, int n_in,
                              void* d_out, int out_size) {
    const float* POI   = (const float*)d_in[0];
    const float* ddis  = (const float*)d_in[1];
    const float* attW  = (const float*)d_in[2];
    const float* a_src = (const float*)d_in[3];
    const float* a_dst = (const float*)d_in[4];
    const float* in_w  = (const float*)d_in[5];
    const float* in_b  = (const float*)d_in[6];
    const float* out_w = (const float*)d_in[7];
    const float* out_b = (const float*)d_in[8];
    const float* ln1g  = (const float*)d_in[9];
    const float* ln1b  = (const float*)d_in[10];
    const float* ln2g  = (const float*)d_in[11];
    const float* ln2b  = (const float*)d_in[12];
    const float* w1    = (const float*)d_in[13];
    const float* b1    = (const float*)d_in[14];
    const float* w2    = (const float*)d_in[15];
    const float* b2    = (const float*)d_in[16];
    const int* sess  = (const int*)d_in[17];
    const int* edist = (const int*)d_in[18];
    const int* bids  = (const int*)d_in[20];
    const int* npos  = (const int*)d_in[21];
    const int* lens  = (const int*)d_in[22];
    int N = in_sizes[17];
    int V = in_sizes[0] / D;

    float *pH, *pQn, *pq, *pctx, *po2, *pf1, *pfin;
    uint32_t* pWf;
    cudaGetSymbolAddress((void**)&pH, g_H);
    cudaGetSymbolAddress((void**)&pQn, g_Qn);
    cudaGetSymbolAddress((void**)&pq, g_q);
    cudaGetSymbolAddress((void**)&pctx, g_ctx);
    cudaGetSymbolAddress((void**)&po2, g_o2);
    cudaGetSymbolAddress((void**)&pf1, g_f1);
    cudaGetSymbolAddress((void**)&pfin, g_fin);
    cudaGetSymbolAddress((void**)&pWf, g_Wfrag);

    size_t gsh = GEMM_SMEM_BYTES;                                  // ~99 KB
    cudaFuncSetAttribute(gemm_fused, cudaFuncAttributeMaxDynamicSharedMemorySize, (int)gsh);
    cudaFuncSetAttribute(gemm_qkv, cudaFuncAttributeMaxDynamicSharedMemorySize, (int)gsh);
    size_t ash = (size_t)(2 * MAXKT * 256) * sizeof(uint32_t);     // 40 KB
    cudaFuncSetAttribute(attn_tc, cudaFuncAttributeMaxDynamicSharedMemorySize, (int)ash);

    int pv_blocks = (V + 7) / 8;
    k_cvec<<<1, 128>>>(attW, a_src, a_dst);
    k_pre2<<<5 + 384 + pv_blocks, 256>>>(ddis, lens, in_w, out_w, w1, w2, POI, V);
    k_node<<<(N + 7) / 8, 256>>>(POI, sess, edist, bids, npos, lens, ln1g, ln1b, N);

    int gb = (N + 63) / 64;
    gemm_qkv<<<gb, 256, gsh>>>(pH, pQn, in_b, N);
    attn_tc<<<dim3(BATCH, 4), 128, ash>>>(lens);
    // out-proj + residual(Qn) + LN2 fused
    gemm_fused<<<gb, 256, gsh>>>(pctx, pWf + 3 * D * D, out_b, pQn, ln2g, ln2b, po2, N, 3);
    // FFN
    gemm_fused<<<gb, 256, gsh>>>(po2, pWf + 4 * D * D, b1, nullptr, nullptr, nullptr, pf1, N, 1);
    gemm_fused<<<gb, 256, gsh>>>(pf1, pWf + 5 * D * D, b2, po2, nullptr, nullptr, pfin, N, 2);
    k_pool<<<(BATCH + 7) / 8, 256>>>(lens, (float*)d_out);
}

// round 6
// speedup vs baseline: 2.8215x; 1.0905x over previous
#include <cuda_runtime.h>
#include <math.h>
#include <stdint.h>

#define D 128
#define BATCH 1024
#define MAXLEN 160
#define NMAX 114000
#define VMAX 50048
#define MAXKT 20

// ---------------- device scratch ----------------
__device__ __align__(16) float g_csrc[D];
__device__ __align__(16) float g_cdst[D];
__device__ __align__(16) float g_ddot[512];
__device__ __align__(16) float g_pvs[VMAX];
__device__ __align__(16) float g_pvd[VMAX];
__device__ int   g_starts[BATCH];
__device__ __align__(16) uint32_t g_Wfrag[6 * D * D];   // tf32 fragment-ordered: q,k,v,o,f1,f2
__device__ __align__(16) float g_Qn [(size_t)NMAX * D];
__device__ __align__(16) float g_q  [(size_t)NMAX * D];
__device__ __align__(16) float g_k  [(size_t)NMAX * D];
__device__ __align__(16) float g_v  [(size_t)NMAX * D];
__device__ __align__(16) float g_ctx[(size_t)NMAX * D];
__device__ __align__(16) float g_o2 [(size_t)NMAX * D];
__device__ __align__(16) float g_fin[(size_t)NMAX * D];

__device__ __forceinline__ float wsum(float v) {
#pragma unroll
    for (int o = 16; o; o >>= 1) v += __shfl_xor_sync(0xffffffffu, v, o);
    return v;
}
__device__ __forceinline__ uint32_t f2tf32(float f) {
    uint32_t u;
    asm("cvt.rna.tf32.f32 %0, %1;" : "=r"(u) : "f"(f));
    return u;
}
__device__ __forceinline__ uint32_t smem_u32(const void* p) {
    return (uint32_t)__cvta_generic_to_shared(p);
}
#define MMA_TF32(c0,c1,c2,c3,a0,a1,a2,a3,b0,b1) \
    asm volatile("mma.sync.aligned.m16n8k8.row.col.f32.tf32.tf32.f32 " \
                 "{%0,%1,%2,%3}, {%4,%5,%6,%7}, {%8,%9}, {%0,%1,%2,%3};" \
                 : "+f"(c0), "+f"(c1), "+f"(c2), "+f"(c3) \
                 : "r"(a0), "r"(a1), "r"(a2), "r"(a3), "r"(b0), "r"(b1))

#define SB_WORDS 16384
#define SA_WORDS (64 * 132)
#define RED_WORDS 512
#define GEMM_SMEM_BYTES ((SB_WORDS + SA_WORDS + RED_WORDS) * 4)

// ---------------- precompute: c vectors ----------------
__global__ void k_cvec(const float* __restrict__ W, const float* __restrict__ as,
                       const float* __restrict__ ad) {
    int k = threadIdx.x;
    float s = 0.f, d = 0.f;
    for (int j = 0; j < D; j++) {
        float w = W[j * D + k];
        s += as[j] * w;
        d += ad[j] * w;
    }
    g_csrc[k] = s;
    g_cdst[k] = d;
}

// ---------------- merged precompute: ddot, starts, weight frags, pv ----------------
__global__ void k_pre2(const float* __restrict__ dd, const int* __restrict__ lens,
                       const float* __restrict__ in_w, const float* __restrict__ out_w,
                       const float* __restrict__ w1, const float* __restrict__ w2,
                       const float* __restrict__ POI, int V) {
    int blk = blockIdx.x;
    int tid = threadIdx.x;
    if (blk < 4) {
        int t = blk * 128 + (tid & 127);
        if (tid < 128) {
            float s = 0.f;
            for (int k = 0; k < D; k++) s += dd[t * D + k] * g_csrc[k];
            g_ddot[t] = s;
        }
    } else if (blk == 4) {
        __shared__ int sl[BATCH];
        for (int i = tid; i < BATCH; i += 256) sl[i] = lens[i];
        __syncthreads();
        if (tid == 0) {
            int s = 0;
            for (int i = 0; i < BATCH; i++) { int t = sl[i]; sl[i] = s; s += t; }
        }
        __syncthreads();
        for (int i = tid; i < BATCH; i += 256) g_starts[i] = sl[i];
    } else if (blk < 5 + 6 * 64) {
        int bb = blk - 5;
        int m = bb >> 6;
        int e = ((bb & 63) << 8) + tid;
        int k = e >> 7, n = e & 127;
        const float* src;
        if (m < 3) src = in_w + m * D * D;
        else if (m == 3) src = out_w;
        else if (m == 4) src = w1;
        else src = w2;
        float v = src[n * D + k];
        int fo = (((k >> 3) << 4) + (n >> 3)) * 64 + ((n & 7) << 3) + ((k & 3) << 1) + ((k >> 2) & 1);
        g_Wfrag[m * D * D + fo] = f2tf32(v);
    } else {
        int v = (blk - (5 + 384)) * 8 + (tid >> 5);
        int lane = tid & 31;
        if (v >= V) return;
        float4 x  = ((const float4*)POI)[(size_t)v * 32 + lane];
        float4 cs = ((const float4*)g_csrc)[lane];
        float4 cd = ((const float4*)g_cdst)[lane];
        float ps = wsum(x.x * cs.x + x.y * cs.y + x.z * cs.z + x.w * cs.w);
        float pd = wsum(x.x * cd.x + x.y * cd.y + x.z * cd.z + x.w * cd.w);
        if (lane == 0) { g_pvs[v] = ps; g_pvd[v] = pd; }
    }
}

// ---------------- GEMM building blocks ----------------
__device__ __forceinline__ void copyB(uint32_t* sB, const uint32_t* __restrict__ Bf, int tid) {
#pragma unroll
    for (int i = 0; i < 16; i++)
        ((uint4*)sB)[tid + 256 * i] = ((const uint4*)Bf)[tid + 256 * i];
}

__device__ __forceinline__ void stageA64(uint32_t* sA, const float* __restrict__ A,
                                         int row0, int N, int tid) {
#pragma unroll
    for (int i = 0; i < 8; i++) {
        int idx = tid + 256 * i;
        int r = idx >> 5, c4 = idx & 31;
        float4 v = make_float4(0.f, 0.f, 0.f, 0.f);
        if (row0 + r < N) v = ((const float4*)A)[((size_t)(row0 + r) << 5) + c4];
        uint4 p;
        p.x = f2tf32(v.x); p.y = f2tf32(v.y); p.z = f2tf32(v.z); p.w = f2tf32(v.w);
        ((uint4*)sA)[r * 33 + c4] = p;
    }
}

// mainloop with ldmatrix A loads. warp layout: wr=warp>>2 (2 row bands of 32), wc=warp&3 (4 col bands)
__device__ __forceinline__ void mmaTile64(const uint32_t* sA, const uint32_t* sB,
                                          int warp, int lane, float acc[2][4][4]) {
    int wr = warp >> 2, wc = warp & 3;
#pragma unroll
    for (int mg = 0; mg < 2; mg++)
#pragma unroll
        for (int nt = 0; nt < 4; nt++)
#pragma unroll
            for (int m = 0; m < 4; m++) acc[mg][nt][m] = 0.f;
    int row_off = lane & 15;
    int col_off = (lane >> 4) << 2;
    uint32_t abase = smem_u32(sA) + (((wr * 32 + row_off) * 132 + col_off) << 2);
    const uint32_t* sBw = sB + (wc << 8) + (lane << 1);
#pragma unroll
    for (int ks = 0; ks < 16; ks++) {
        uint32_t a[2][4];
#pragma unroll
        for (int mg = 0; mg < 2; mg++) {
            uint32_t ad = abase + mg * (16 * 132 * 4) + ks * 32;
            asm volatile("ldmatrix.sync.aligned.m8n8.x4.shared.b16 {%0,%1,%2,%3}, [%4];"
                         : "=r"(a[mg][0]), "=r"(a[mg][1]), "=r"(a[mg][2]), "=r"(a[mg][3])
                         : "r"(ad));
        }
        const uint32_t* bp = sBw + (ks << 10);
#pragma unroll
        for (int nt = 0; nt < 4; nt++) {
            uint2 b = *(const uint2*)(bp + (nt << 6));
#pragma unroll
            for (int mg = 0; mg < 2; mg++)
                MMA_TF32(acc[mg][nt][0], acc[mg][nt][1], acc[mg][nt][2], acc[mg][nt][3],
                         a[mg][0], a[mg][1], a[mg][2], a[mg][3], b.x, b.y);
        }
    }
}

__device__ __forceinline__ void epi64(float acc[2][4][4], const float* __restrict__ bias,
                                      const float* __restrict__ res, float* __restrict__ C,
                                      int row0, int warp, int lane, int N, bool relu) {
    int g = lane >> 2, t = lane & 3;
    int wr = warp >> 2, wc = warp & 3;
#pragma unroll
    for (int mg = 0; mg < 2; mg++) {
        int r1 = row0 + wr * 32 + mg * 16 + g;
        int r2 = r1 + 8;
#pragma unroll
        for (int nt = 0; nt < 4; nt++) {
            int col = wc * 32 + (nt << 3) + (t << 1);
            float2 bb = *(const float2*)(bias + col);
            float2 o1 = make_float2(acc[mg][nt][0] + bb.x, acc[mg][nt][1] + bb.y);
            float2 o2 = make_float2(acc[mg][nt][2] + bb.x, acc[mg][nt][3] + bb.y);
            if (relu) {
                o1.x = fmaxf(o1.x, 0.f); o1.y = fmaxf(o1.y, 0.f);
                o2.x = fmaxf(o2.x, 0.f); o2.y = fmaxf(o2.y, 0.f);
            }
            if (r1 < N) {
                if (res) { float2 rv = *(const float2*)(res + (size_t)r1 * D + col); o1.x += rv.x; o1.y += rv.y; }
                *(float2*)(C + (size_t)r1 * D + col) = o1;
            }
            if (r2 < N) {
                if (res) { float2 rv = *(const float2*)(res + (size_t)r2 * D + col); o2.x += rv.x; o2.y += rv.y; }
                *(float2*)(C + (size_t)r2 * D + col) = o2;
            }
        }
    }
}

// ---------------- fused GCN + LN1 + QKV projections ----------------
// Staging computes H rows in-CTA (fp32, mma truncates to tf32); LN phase rewrites sA with Qn.
__global__ void __launch_bounds__(256, 2) qkv_fused(
    const float* __restrict__ POI, const int* __restrict__ sess,
    const int* __restrict__ edist, const int* __restrict__ bids,
    const int* __restrict__ npos, const int* __restrict__ lens,
    const float* __restrict__ in_b, const float* __restrict__ g1,
    const float* __restrict__ b1v, int N) {
    extern __shared__ uint32_t sm_u[];
    uint32_t* sB = sm_u;
    uint32_t* sA = sm_u + SB_WORDS;
    float* sAf = (float*)sA;
    int tid = threadIdx.x;
    int warp = tid >> 5, lane = tid & 31;
    int row0 = blockIdx.x << 6;

    copyB(sB, g_Wfrag + 1 * D * D, tid);     // Wk
    // ---- stage H rows (GCN 2-way softmax); warp w owns rows w, w+8, ..., w+56 ----
#pragma unroll
    for (int i = 0; i < 8; i++) {
        int r = warp + i * 8;
        int n = row0 + r;
        float4 hv = make_float4(0.f, 0.f, 0.f, 0.f);
        if (n < N) {
            int b = bids[n], p = npos[n], l = lens[b];
            int vi = sess[n];
            bool hasF = (p > 0);
            bool hasB = (p < l - 1);
            float lf = hasF ? (g_pvs[vi] + g_ddot[edist[n - b - 1]]) : -3.0e38f;
            float lb = hasB ? g_pvd[vi] : -3.0e38f;
            float m = fmaxf(lf, lb);
            float ef = hasF ? __expf(lf - m) : 0.f;
            float eb = hasB ? __expf(lb - m) : 0.f;
            float inv = 1.f / (ef + eb + 1e-16f);
            if (hasF) {
                float4 xm = ((const float4*)POI)[(size_t)sess[n - 1] * 32 + lane];
                hv.x = ef * xm.x; hv.y = ef * xm.y; hv.z = ef * xm.z; hv.w = ef * xm.w;
            }
            if (hasB) {
                float4 xp = ((const float4*)POI)[(size_t)sess[n + 1] * 32 + lane];
                hv.x += eb * xp.x; hv.y += eb * xp.y; hv.z += eb * xp.z; hv.w += eb * xp.w;
            }
            hv.x *= inv; hv.y *= inv; hv.z *= inv; hv.w *= inv;
        }
        ((float4*)sAf)[r * 33 + lane] = hv;
    }
    __syncthreads();

    float acc[2][4][4];
    // K pass
    mmaTile64(sA, sB, warp, lane, acc);
    epi64(acc, in_b + D, nullptr, g_k, row0, warp, lane, N, false);
    __syncthreads();
    copyB(sB, g_Wfrag + 2 * D * D, tid);     // Wv
    __syncthreads();
    // V pass
    mmaTile64(sA, sB, warp, lane, acc);
    epi64(acc, in_b + 2 * D, nullptr, g_v, row0, warp, lane, N, false);
    __syncthreads();

    // ---- LN1 in-place: sA rows -> Qn (also write to g_Qn for later residual) ----
    {
        float4 gg = ((const float4*)g1)[lane];
        float4 bb = ((const float4*)b1v)[lane];
#pragma unroll
        for (int i = 0; i < 8; i++) {
            int r = warp + i * 8;
            float4 hv = ((float4*)sAf)[r * 33 + lane];
            float mean = wsum(hv.x + hv.y + hv.z + hv.w) * (1.f / 128.f);
            float4 dx = make_float4(hv.x - mean, hv.y - mean, hv.z - mean, hv.w - mean);
            float var = wsum(dx.x * dx.x + dx.y * dx.y + dx.z * dx.z + dx.w * dx.w) * (1.f / 128.f);
            float rs = rsqrtf(var + 1e-8f);
            float4 qn = make_float4(dx.x * rs * gg.x + bb.x, dx.y * rs * gg.y + bb.y,
                                    dx.z * rs * gg.z + bb.z, dx.w * rs * gg.w + bb.w);
            ((float4*)sAf)[r * 33 + lane] = qn;
            int n = row0 + r;
            if (n < N) ((float4*)g_Qn)[((size_t)n << 5) + lane] = qn;
        }
    }
    copyB(sB, g_Wfrag + 0 * D * D, tid);     // Wq
    __syncthreads();
    // Q pass
    mmaTile64(sA, sB, warp, lane, acc);
    epi64(acc, in_b, nullptr, g_q, row0, warp, lane, N, false);
}

// ---------------- generic GEMM (mode 3 = bias+res+LayerNorm2) ----------------
__global__ void __launch_bounds__(256, 2) gemm_fused(
    const float* __restrict__ A, const uint32_t* __restrict__ Bfrag,
    const float* __restrict__ bias, const float* __restrict__ res,
    const float* __restrict__ lng, const float* __restrict__ lnb,
    float* __restrict__ C, int N, int mode) {
    extern __shared__ uint32_t sm_u[];
    uint32_t* sB = sm_u;
    uint32_t* sA = sm_u + SB_WORDS;
    float* red = (float*)(sm_u + SB_WORDS + SA_WORDS);
    int tid = threadIdx.x;
    copyB(sB, Bfrag, tid);
    int row0 = blockIdx.x << 6;
    stageA64(sA, A, row0, N, tid);
    __syncthreads();

    int warp = tid >> 5, lane = tid & 31;
    float acc[2][4][4];
    mmaTile64(sA, sB, warp, lane, acc);

    if (mode != 3) {
        epi64(acc, bias, res, C, row0, warp, lane, N, mode == 1);
        return;
    }
    int g = lane >> 2, t = lane & 3;
    int wr = warp >> 2, wc = warp & 3;
#pragma unroll
    for (int mg = 0; mg < 2; mg++) {
        int r1 = row0 + wr * 32 + mg * 16 + g;
        int r2 = r1 + 8;
        float s1 = 0.f, s2 = 0.f, q1 = 0.f, q2 = 0.f;
#pragma unroll
        for (int nt = 0; nt < 4; nt++) {
            int col = wc * 32 + (nt << 3) + (t << 1);
            float2 bb = *(const float2*)(bias + col);
            float2 rv1 = make_float2(0.f, 0.f), rv2 = make_float2(0.f, 0.f);
            if (r1 < N) rv1 = *(const float2*)(res + (size_t)r1 * D + col);
            if (r2 < N) rv2 = *(const float2*)(res + (size_t)r2 * D + col);
            acc[mg][nt][0] += bb.x + rv1.x; acc[mg][nt][1] += bb.y + rv1.y;
            acc[mg][nt][2] += bb.x + rv2.x; acc[mg][nt][3] += bb.y + rv2.y;
            s1 += acc[mg][nt][0] + acc[mg][nt][1];
            s2 += acc[mg][nt][2] + acc[mg][nt][3];
            q1 += acc[mg][nt][0] * acc[mg][nt][0] + acc[mg][nt][1] * acc[mg][nt][1];
            q2 += acc[mg][nt][2] * acc[mg][nt][2] + acc[mg][nt][3] * acc[mg][nt][3];
        }
        s1 += __shfl_xor_sync(0xffffffffu, s1, 1); s1 += __shfl_xor_sync(0xffffffffu, s1, 2);
        s2 += __shfl_xor_sync(0xffffffffu, s2, 1); s2 += __shfl_xor_sync(0xffffffffu, s2, 2);
        q1 += __shfl_xor_sync(0xffffffffu, q1, 1); q1 += __shfl_xor_sync(0xffffffffu, q1, 2);
        q2 += __shfl_xor_sync(0xffffffffu, q2, 1); q2 += __shfl_xor_sync(0xffffffffu, q2, 2);
        if (t == 0) {
            int lr1 = wr * 32 + mg * 16 + g;
            red[lr1 * 4 + wc] = s1;
            red[(lr1 + 8) * 4 + wc] = s2;
            red[256 + lr1 * 4 + wc] = q1;
            red[256 + (lr1 + 8) * 4 + wc] = q2;
        }
    }
    __syncthreads();
#pragma unroll
    for (int mg = 0; mg < 2; mg++) {
        int lr1 = wr * 32 + mg * 16 + g;
        int r1 = row0 + lr1, r2 = r1 + 8;
        float s1 = red[lr1 * 4] + red[lr1 * 4 + 1] + red[lr1 * 4 + 2] + red[lr1 * 4 + 3];
        float s2 = red[(lr1 + 8) * 4] + red[(lr1 + 8) * 4 + 1] + red[(lr1 + 8) * 4 + 2] + red[(lr1 + 8) * 4 + 3];
        float q1 = red[256 + lr1 * 4] + red[256 + lr1 * 4 + 1] + red[256 + lr1 * 4 + 2] + red[256 + lr1 * 4 + 3];
        float q2 = red[256 + (lr1 + 8) * 4] + red[256 + (lr1 + 8) * 4 + 1] + red[256 + (lr1 + 8) * 4 + 2] + red[256 + (lr1 + 8) * 4 + 3];
        float m1 = s1 * (1.f / 128.f), m2 = s2 * (1.f / 128.f);
        float v1 = q1 * (1.f / 128.f) - m1 * m1;
        float v2 = q2 * (1.f / 128.f) - m2 * m2;
        float rr1 = rsqrtf(fmaxf(v1, 0.f) + 1e-8f);
        float rr2 = rsqrtf(fmaxf(v2, 0.f) + 1e-8f);
#pragma unroll
        for (int nt = 0; nt < 4; nt++) {
            int col = wc * 32 + (nt << 3) + (t << 1);
            float2 gg = *(const float2*)(lng + col);
            float2 be = *(const float2*)(lnb + col);
            if (r1 < N) {
                float2 o = make_float2((acc[mg][nt][0] - m1) * rr1 * gg.x + be.x,
                                       (acc[mg][nt][1] - m1) * rr1 * gg.y + be.y);
                *(float2*)(C + (size_t)r1 * D + col) = o;
            }
            if (r2 < N) {
                float2 o = make_float2((acc[mg][nt][2] - m2) * rr2 * gg.x + be.x,
                                       (acc[mg][nt][3] - m2) * rr2 * gg.y + be.y);
                *(float2*)(C + (size_t)r2 * D + col) = o;
            }
        }
    }
}

// ---------------- fused FFN: fin = relu(o2@W1+b1)@W2 + b2 + o2 ----------------
__global__ void __launch_bounds__(256, 2) ffn_fused(
    const float* __restrict__ o2, const uint32_t* __restrict__ Wf1,
    const uint32_t* __restrict__ Wf2, const float* __restrict__ b1,
    const float* __restrict__ b2, int N) {
    extern __shared__ uint32_t sm_u[];
    uint32_t* sB = sm_u;
    uint32_t* sA = sm_u + SB_WORDS;
    int tid = threadIdx.x;
    int warp = tid >> 5, lane = tid & 31;
    int row0 = blockIdx.x << 6;

    copyB(sB, Wf1, tid);
    stageA64(sA, o2, row0, N, tid);
    __syncthreads();

    float acc[2][4][4];
    mmaTile64(sA, sB, warp, lane, acc);
    __syncthreads();                     // all warps done reading sA/sB

    // relu(acc + b1) back into sA (tf32), and load W2
    {
        int g = lane >> 2, t = lane & 3;
        int wr = warp >> 2, wc = warp & 3;
#pragma unroll
        for (int mg = 0; mg < 2; mg++) {
            int lr1 = wr * 32 + mg * 16 + g;
            int lr2 = lr1 + 8;
#pragma unroll
            for (int nt = 0; nt < 4; nt++) {
                int col = wc * 32 + (nt << 3) + (t << 1);
                float2 bb = *(const float2*)(b1 + col);
                uint2 v1, v2;
                v1.x = f2tf32(fmaxf(acc[mg][nt][0] + bb.x, 0.f));
                v1.y = f2tf32(fmaxf(acc[mg][nt][1] + bb.y, 0.f));
                v2.x = f2tf32(fmaxf(acc[mg][nt][2] + bb.x, 0.f));
                v2.y = f2tf32(fmaxf(acc[mg][nt][3] + bb.y, 0.f));
                *(uint2*)(sA + lr1 * 132 + col) = v1;
                *(uint2*)(sA + lr2 * 132 + col) = v2;
            }
        }
    }
    copyB(sB, Wf2, tid);
    __syncthreads();

    mmaTile64(sA, sB, warp, lane, acc);
    epi64(acc, b2, o2, g_fin, row0, warp, lane, N, false);
}

// ---------------- tensor-core flash attention, CTA per (session, head) ----------------
__global__ void __launch_bounds__(128) attn_tc(const int* __restrict__ lens) {
    extern __shared__ uint32_t smA[];
    uint32_t* sKf = smA;
    uint32_t* sVf = smA + MAXKT * 256;
    int b = blockIdx.x, h = blockIdx.y;
    int l = lens[b];
    int start = g_starts[b];
    int nkt = (l + 7) >> 3, nqt = (l + 15) >> 4;
    int tid = threadIdx.x, w = tid >> 5, lane = tid & 31;
    int g = lane >> 2, t = lane & 3;
    const float qscale = 0.17677669529663687f;

    int tot = nkt * 256;
    for (int idx = tid; idx < tot; idx += 128) {
        int j = idx >> 5, c = idx & 31;
        float kvf = 0.f, vvf = 0.f;
        if (j < l) {
            size_t off = (size_t)(start + j) * D + h * 32 + c;
            kvf = g_k[off];
            vvf = g_v[off];
        }
        int base = (j >> 3) * 256;
        int fk = base + (c >> 3) * 64 + ((j & 7) << 3) + ((c & 3) << 1) + ((c >> 2) & 1);
        int fv = base + (c >> 3) * 64 + ((c & 7) << 3) + ((j & 3) << 1) + ((j >> 2) & 1);
        sKf[fk] = f2tf32(kvf);
        sVf[fv] = f2tf32(vvf);
    }
    __syncthreads();

    int srcidx = (g << 2) + (t >> 1);
    bool odd = t & 1;

    for (int qt = w; qt < nqt; qt += 4) {
        int r0 = qt * 16;
        uint32_t qa[4][4];
#pragma unroll
        for (int kc = 0; kc < 4; kc++) {
            int c = kc * 8 + t;
            size_t ro = (size_t)(start + r0 + g) * D + h * 32 + c;
            size_t ro8 = ro + (size_t)8 * D;
            qa[kc][0] = f2tf32(g_q[ro] * qscale);
            qa[kc][1] = f2tf32(g_q[ro8] * qscale);
            qa[kc][2] = f2tf32(g_q[ro + 4] * qscale);
            qa[kc][3] = f2tf32(g_q[ro8 + 4] * qscale);
        }
        float o[4][4];
#pragma unroll
        for (int nc = 0; nc < 4; nc++)
#pragma unroll
            for (int m = 0; m < 4; m++) o[nc][m] = 0.f;
        float mr0 = -3.0e38f, mr1 = -3.0e38f, sr0 = 0.f, sr1 = 0.f;

        for (int kt = 0; kt < nkt; kt++) {
            float s0 = 0.f, s1 = 0.f, s2 = 0.f, s3 = 0.f;
            const uint32_t* kp = sKf + kt * 256 + (lane << 1);
#pragma unroll
            for (int kc = 0; kc < 4; kc++) {
                uint2 bb = *(const uint2*)(kp + (kc << 6));
                MMA_TF32(s0, s1, s2, s3, qa[kc][0], qa[kc][1], qa[kc][2], qa[kc][3], bb.x, bb.y);
            }
            int col0 = kt * 8 + 2 * t;
            if (col0 >= l)     { s0 = -3.0e38f; s2 = -3.0e38f; }
            if (col0 + 1 >= l) { s1 = -3.0e38f; s3 = -3.0e38f; }
            float tm0 = fmaxf(s0, s1), tm1 = fmaxf(s2, s3);
            tm0 = fmaxf(tm0, __shfl_xor_sync(0xffffffffu, tm0, 1));
            tm0 = fmaxf(tm0, __shfl_xor_sync(0xffffffffu, tm0, 2));
            tm1 = fmaxf(tm1, __shfl_xor_sync(0xffffffffu, tm1, 1));
            tm1 = fmaxf(tm1, __shfl_xor_sync(0xffffffffu, tm1, 2));
            float mn0 = fmaxf(mr0, tm0), mn1 = fmaxf(mr1, tm1);
            float al0 = __expf(mr0 - mn0), al1 = __expf(mr1 - mn1);
            mr0 = mn0; mr1 = mn1;
            float p0 = __expf(s0 - mn0), p1 = __expf(s1 - mn0);
            float p2 = __expf(s2 - mn1), p3 = __expf(s3 - mn1);
            float ts0 = p0 + p1, ts1 = p2 + p3;
            ts0 += __shfl_xor_sync(0xffffffffu, ts0, 1);
            ts0 += __shfl_xor_sync(0xffffffffu, ts0, 2);
            ts1 += __shfl_xor_sync(0xffffffffu, ts1, 1);
            ts1 += __shfl_xor_sync(0xffffffffu, ts1, 2);
            sr0 = sr0 * al0 + ts0;
            sr1 = sr1 * al1 + ts1;
#pragma unroll
            for (int nc = 0; nc < 4; nc++) {
                o[nc][0] *= al0; o[nc][1] *= al1;
                o[nc][2] *= al0; o[nc][3] *= al1;
            }
            float h0a = __shfl_sync(0xffffffffu, p0, srcidx);
            float h1a = __shfl_sync(0xffffffffu, p1, srcidx);
            float h0b = __shfl_sync(0xffffffffu, p0, srcidx + 2);
            float h1b = __shfl_sync(0xffffffffu, p1, srcidx + 2);
            float h2a = __shfl_sync(0xffffffffu, p2, srcidx);
            float h3a = __shfl_sync(0xffffffffu, p3, srcidx);
            float h2b = __shfl_sync(0xffffffffu, p2, srcidx + 2);
            float h3b = __shfl_sync(0xffffffffu, p3, srcidx + 2);
            uint32_t pa0 = f2tf32(odd ? h1a : h0a);
            uint32_t pa1 = f2tf32(odd ? h3a : h2a);
            uint32_t pa2 = f2tf32(odd ? h1b : h0b);
            uint32_t pa3 = f2tf32(odd ? h3b : h2b);
            const uint32_t* vp = sVf + kt * 256 + (lane << 1);
#pragma unroll
            for (int nc = 0; nc < 4; nc++) {
                uint2 vb = *(const uint2*)(vp + (nc << 6));
                MMA_TF32(o[nc][0], o[nc][1], o[nc][2], o[nc][3],
                         pa0, pa1, pa2, pa3, vb.x, vb.y);
            }
        }
        float inv0 = 1.f / sr0, inv1 = 1.f / sr1;
        int rr = r0 + g;
#pragma unroll
        for (int nc = 0; nc < 4; nc++) {
            int col = h * 32 + nc * 8 + 2 * t;
            if (rr < l)
                *(float2*)(g_ctx + (size_t)(start + rr) * D + col) =
                    make_float2(o[nc][0] * inv0, o[nc][1] * inv0);
            if (rr + 8 < l)
                *(float2*)(g_ctx + (size_t)(start + rr + 8) * D + col) =
                    make_float2(o[nc][2] * inv1, o[nc][3] * inv1);
        }
    }
}

// ---------------- masked mean pool ----------------
__global__ void k_pool(const int* __restrict__ lens, float* __restrict__ out) {
    int b = (blockIdx.x * blockDim.x + threadIdx.x) >> 5;
    int lane = threadIdx.x & 31;
    if (b >= BATCH) return;
    int l = lens[b], s = g_starts[b];
    float4 acc = make_float4(0.f, 0.f, 0.f, 0.f);
    for (int p = 0; p < l; p++) {
        float4 v = ((const float4*)g_fin)[(size_t)(s + p) * 32 + lane];
        acc.x += v.x; acc.y += v.y; acc.z += v.z; acc.w += v.w;
    }
    float iv = 1.f / (float)l;
    ((float4*)out)[b * 32 + lane] =
        make_float4(acc.x * iv, acc.y * iv, acc.z * iv, acc.w * iv);
}

// ---------------- launch ----------------
extern "C" void kernel_launch(void* const* d_in, const int* in_sizes, int n_in,
                              void* d_out, int out_size) {
    const float* POI   = (const float*)d_in[0];
    const float* ddis  = (const float*)d_in[1];
    const float* attW  = (const float*)d_in[2];
    const float* a_src = (const float*)d_in[3];
    const float* a_dst = (const float*)d_in[4];
    const float* in_w  = (const float*)d_in[5];
    const float* in_b  = (const float*)d_in[6];
    const float* out_w = (const float*)d_in[7];
    const float* out_b = (const float*)d_in[8];
    const float* ln1g  = (const float*)d_in[9];
    const float* ln1b  = (const float*)d_in[10];
    const float* ln2g  = (const float*)d_in[11];
    const float* ln2b  = (const float*)d_in[12];
    const float* w1    = (const float*)d_in[13];
    const float* b1    = (const float*)d_in[14];
    const float* w2    = (const float*)d_in[15];
    const float* b2    = (const float*)d_in[16];
    const int* sess  = (const int*)d_in[17];
    const int* edist = (const int*)d_in[18];
    const int* bids  = (const int*)d_in[20];
    const int* npos  = (const int*)d_in[21];
    const int* lens  = (const int*)d_in[22];
    int N = in_sizes[17];
    int V = in_sizes[0] / D;

    float *pQn, *pctx, *po2;
    uint32_t* pWf;
    cudaGetSymbolAddress((void**)&pQn, g_Qn);
    cudaGetSymbolAddress((void**)&pctx, g_ctx);
    cudaGetSymbolAddress((void**)&po2, g_o2);
    cudaGetSymbolAddress((void**)&pWf, g_Wfrag);

    size_t gsh = GEMM_SMEM_BYTES;                                  // ~99 KB
    cudaFuncSetAttribute(qkv_fused, cudaFuncAttributeMaxDynamicSharedMemorySize, (int)gsh);
    cudaFuncSetAttribute(gemm_fused, cudaFuncAttributeMaxDynamicSharedMemorySize, (int)gsh);
    cudaFuncSetAttribute(ffn_fused, cudaFuncAttributeMaxDynamicSharedMemorySize, (int)gsh);
    size_t ash = (size_t)(2 * MAXKT * 256) * sizeof(uint32_t);     // 40 KB
    cudaFuncSetAttribute(attn_tc, cudaFuncAttributeMaxDynamicSharedMemorySize, (int)ash);

    int pv_blocks = (V + 7) / 8;
    k_cvec<<<1, 128>>>(attW, a_src, a_dst);
    k_pre2<<<5 + 384 + pv_blocks, 256>>>(ddis, lens, in_w, out_w, w1, w2, POI, V);

    int gb = (N + 63) / 64;
    qkv_fused<<<gb, 256, gsh>>>(POI, sess, edist, bids, npos, lens, in_b, ln1g, ln1b, N);
    attn_tc<<<dim3(BATCH, 4), 128, ash>>>(lens);
    gemm_fused<<<gb, 256, gsh>>>(pctx, pWf + 3 * D * D, out_b, pQn, ln2g, ln2b, po2, N, 3);
    ffn_fused<<<gb, 256, gsh>>>(po2, pWf + 4 * D * D, pWf + 5 * D * D, b1, b2, N);
    k_pool<<<(BATCH + 7) / 8, 256>>>(lens, (float*)d_out);
}